// round 3
// baseline (speedup 1.0000x reference)
#include <cuda_runtime.h>
#include <math.h>

// Problem constants (fixed by the reference)
#define N_NODES 100000
#define E_EDGES 3200000
#define DD 256           // feature dim

// ---------------- scratch (static device allocations; no cudaMalloc) -------
__device__ int   g_is64;                 // 1 if edge_index buffer is int64
__device__ int   g_src [E_EDGES];        // decoded edge sources
__device__ int   g_dst [E_EDGES];        // decoded edge destinations
__device__ int   g_cnt [N_NODES];        // in-degree (edges only)
__device__ int   g_off [N_NODES + 1];    // CSR row offsets (by dst)
__device__ int   g_cur [N_NODES];        // fill cursors
__device__ int   g_esrc[E_EDGES];        // src node id per CSR slot
__device__ float g_dis [N_NODES];        // rsqrt(deg)
__device__ float g_xw  [N_NODES * DD];   // x @ W  (per layer)
__device__ float g_h   [N_NODES * DD];   // layer-1 activations

// ---------------------------------------------------------------------------
// Detect int32 vs int64 edge_index. In int64 little-endian layout, every odd
// int32 word is a high word == 0 (ids < 2^31). In int32 layout odd words are
// random node ids -> essentially impossible that 2048 samples are all zero.
__global__ void k_detect(const int* __restrict__ ei32) {
    __shared__ int nz[256];
    int tid = threadIdx.x;
    int acc = 0;
    for (int i = tid; i < 2048; i += 256)
        acc += (ei32[2 * i + 1] != 0) ? 1 : 0;
    nz[tid] = acc;
    __syncthreads();
    for (int s = 128; s > 0; s >>= 1) {
        if (tid < s) nz[tid] += nz[tid + s];
        __syncthreads();
    }
    if (tid == 0) g_is64 = (nz[0] == 0) ? 1 : 0;
}

// Decode src/dst into int32 arrays (works for both dtypes).
__global__ void k_convert(const int* __restrict__ ei32) {
    int e = blockIdx.x * blockDim.x + threadIdx.x;
    if (e >= E_EDGES) return;
    if (g_is64) {
        // int64 layout: element i occupies words 2i (low), 2i+1 (high)
        g_src[e] = ei32[2 * e];
        g_dst[e] = ei32[2 * (E_EDGES + e)];
    } else {
        g_src[e] = ei32[e];
        g_dst[e] = ei32[E_EDGES + e];
    }
}

// ---------------------------------------------------------------------------
__global__ void k_zero_cnt() {
    int i = blockIdx.x * blockDim.x + threadIdx.x;
    if (i < N_NODES) g_cnt[i] = 0;
}

// cnt[dst[e]] += 1
__global__ void k_count() {
    int e = blockIdx.x * blockDim.x + threadIdx.x;
    if (e < E_EDGES) atomicAdd(&g_cnt[g_dst[e]], 1);
}

// Single-block exclusive scan over g_cnt -> g_off, g_cur; also dis = rsqrt(deg)
__global__ __launch_bounds__(1024)
void k_scan() {
    __shared__ int sums[1024];
    const int tid = threadIdx.x;
    const int CH  = (N_NODES + 1023) / 1024;       // 98
    int beg = tid * CH;
    int end = beg + CH; if (end > N_NODES) end = N_NODES;
    if (beg > N_NODES) beg = N_NODES;

    int s = 0;
    for (int i = beg; i < end; i++) s += g_cnt[i];
    sums[tid] = s;
    __syncthreads();

    for (int off = 1; off < 1024; off <<= 1) {
        int v = (tid >= off) ? sums[tid - off] : 0;
        __syncthreads();
        sums[tid] += v;
        __syncthreads();
    }

    int run = (tid > 0) ? sums[tid - 1] : 0;       // exclusive prefix
    for (int i = beg; i < end; i++) {
        int c = g_cnt[i];
        g_off[i] = run;
        g_cur[i] = run;
        g_dis[i] = rsqrtf((float)(c + 1));         // deg includes self loop
        run += c;
    }
    if (tid == 0) g_off[N_NODES] = sums[1023];
}

// Scatter edge src ids into CSR slots (order within a segment is arbitrary)
__global__ void k_fill() {
    int e = blockIdx.x * blockDim.x + threadIdx.x;
    if (e >= E_EDGES) return;
    int p = atomicAdd(&g_cur[g_dst[e]], 1);
    g_esrc[p] = g_src[e];
}

// ---------------------------------------------------------------------------
// SGEMM: C[M,256] = A[M,256] @ B[256,256], row-major, fp32.
// 128x128 block tile, BK=16, 256 threads, 8x8 per-thread register tile.
__global__ __launch_bounds__(256)
void k_sgemm(const float* __restrict__ A, const float* __restrict__ B,
             float* __restrict__ C, int M) {
    const int BM = 128, BN = 128, BK = 16;
    __shared__ float As[BK][BM];
    __shared__ float Bs[BK][BN];

    int tid = threadIdx.x;
    int bm = blockIdx.y * BM;
    int bn = blockIdx.x * BN;

    int a_row  = tid >> 2;
    int a_col4 = tid & 3;
    int b_row  = tid >> 5;
    int b_col4 = tid & 31;

    int tx = tid & 15;
    int ty = tid >> 4;

    float acc[8][8];
#pragma unroll
    for (int i = 0; i < 8; i++)
#pragma unroll
        for (int j = 0; j < 8; j++) acc[i][j] = 0.0f;

    for (int k0 = 0; k0 < DD; k0 += BK) {
#pragma unroll
        for (int it = 0; it < 2; it++) {
            int r  = a_row + it * 64;
            int gr = bm + r;
            float4 v = make_float4(0.f, 0.f, 0.f, 0.f);
            if (gr < M)
                v = *(const float4*)(A + (size_t)gr * DD + k0 + a_col4 * 4);
            As[a_col4 * 4 + 0][r] = v.x;
            As[a_col4 * 4 + 1][r] = v.y;
            As[a_col4 * 4 + 2][r] = v.z;
            As[a_col4 * 4 + 3][r] = v.w;
        }
#pragma unroll
        for (int it = 0; it < 2; it++) {
            int r = b_row + it * 8;
            float4 v = *(const float4*)(B + (size_t)(k0 + r) * DD + bn + b_col4 * 4);
            *(float4*)(&Bs[r][b_col4 * 4]) = v;
        }
        __syncthreads();

#pragma unroll
        for (int k = 0; k < BK; k++) {
            float ra[8], rb[8];
#pragma unroll
            for (int i = 0; i < 8; i++) ra[i] = As[k][ty * 8 + i];
#pragma unroll
            for (int j = 0; j < 8; j++) rb[j] = Bs[k][tx * 8 + j];
#pragma unroll
            for (int i = 0; i < 8; i++)
#pragma unroll
                for (int j = 0; j < 8; j++)
                    acc[i][j] += ra[i] * rb[j];
        }
        __syncthreads();
    }

#pragma unroll
    for (int i = 0; i < 8; i++) {
        int gr = bm + ty * 8 + i;
        if (gr < M) {
#pragma unroll
            for (int j = 0; j < 8; j += 4) {
                *(float4*)(C + (size_t)gr * DD + bn + tx * 8 + j) =
                    make_float4(acc[i][j], acc[i][j+1], acc[i][j+2], acc[i][j+3]);
            }
        }
    }
}

// ---------------------------------------------------------------------------
// Fused aggregate + bias + ELU. One 256-thread block per destination node;
// thread t owns feature column t. No atomics.
//   out[n,t] = elu( dis[n]^2*xw[n,t] + sum_e dis[n]*dis[src_e]*xw[src_e,t] + b[t] )
__global__ __launch_bounds__(256)
void k_agg(const float* __restrict__ xw, const float* __restrict__ b,
           float* __restrict__ out) {
    int node = blockIdx.x;
    int tid  = threadIdx.x;

    float dn  = g_dis[node];
    float acc = dn * dn * xw[(size_t)node * DD + tid];

    int beg = g_off[node];
    int end = g_off[node + 1];

    int e = beg;
    for (; e + 1 < end; e += 2) {
        int s0 = g_esrc[e];
        int s1 = g_esrc[e + 1];
        float w0 = dn * g_dis[s0];
        float w1 = dn * g_dis[s1];
        float v0 = xw[(size_t)s0 * DD + tid];
        float v1 = xw[(size_t)s1 * DD + tid];
        acc += w0 * v0;
        acc += w1 * v1;
    }
    if (e < end) {
        int s0 = g_esrc[e];
        acc += dn * g_dis[s0] * xw[(size_t)s0 * DD + tid];
    }

    acc += b[tid];
    out[(size_t)node * DD + tid] = acc > 0.f ? acc : expm1f(acc);
}

// ---------------------------------------------------------------------------
extern "C" void kernel_launch(void* const* d_in, const int* in_sizes, int n_in,
                              void* d_out, int out_size) {
    const float* x   = (const float*)d_in[0];
    const int*   ei  = (const int*)d_in[1];    // int32 or int64 (auto-detected)
    const float* W1  = (const float*)d_in[2];
    const float* b1  = (const float*)d_in[3];
    const float* W2  = (const float*)d_in[4];
    const float* b2  = (const float*)d_in[5];
    float*       out = (float*)d_out;

    float* xw = nullptr; cudaGetSymbolAddress((void**)&xw, g_xw);
    float* h  = nullptr; cudaGetSymbolAddress((void**)&h,  g_h);

    const int T = 256;
    int grid_n = (N_NODES + T - 1) / T;
    int grid_e = (E_EDGES + T - 1) / T;
    dim3 gemm_grid(DD / 128, (N_NODES + 127) / 128);

    // --- edge decode + CSR build + normalization (shared by both layers) ---
    k_detect  <<<1, 256>>>(ei);
    k_convert <<<grid_e, T>>>(ei);
    k_zero_cnt<<<grid_n, T>>>();
    k_count   <<<grid_e, T>>>();
    k_scan    <<<1, 1024>>>();
    k_fill    <<<grid_e, T>>>();

    // --- layer 1 ---
    k_sgemm<<<gemm_grid, T>>>(x, W1, xw, N_NODES);
    k_agg  <<<N_NODES, T>>>(xw, b1, h);

    // --- layer 2 ---
    k_sgemm<<<gemm_grid, T>>>(h, W2, xw, N_NODES);
    k_agg  <<<N_NODES, T>>>(xw, b2, out);
}

// round 4
// speedup vs baseline: 2.0600x; 2.0600x over previous
#include <cuda_runtime.h>
#include <math.h>

// Problem constants (fixed by the reference)
#define N_NODES 100000
#define E_EDGES 3200000
#define DD 256           // feature dim
#define D4 (DD/4)        // 64 float4 per row

// ---------------- scratch (static device allocations; no cudaMalloc) -------
__device__ int   g_is64;                 // 1 if edge_index buffer is int64
__device__ int   g_src [E_EDGES];        // decoded edge sources
__device__ int   g_dst [E_EDGES];        // decoded edge destinations
__device__ int   g_cnt [N_NODES];        // in-degree (edges only)
__device__ int   g_off [N_NODES + 1];    // CSR row offsets (by dst)
__device__ int   g_cur [N_NODES];        // fill cursors
__device__ int   g_esrc[E_EDGES];        // src node id per CSR slot
__device__ float g_dis [N_NODES];        // rsqrt(deg)
__device__ float g_xw  [N_NODES * DD];   // dis .* (A @ W)   (per layer)
__device__ float g_h   [N_NODES * DD];   // layer-1 activations

// ---------------------------------------------------------------------------
// Detect int32 vs int64 edge_index (ids < 2^31 -> int64 high words all zero).
__global__ void k_detect(const int* __restrict__ ei32) {
    __shared__ int nz[256];
    int tid = threadIdx.x;
    int acc = 0;
    for (int i = tid; i < 2048; i += 256)
        acc += (ei32[2 * i + 1] != 0) ? 1 : 0;
    nz[tid] = acc;
    __syncthreads();
    for (int s = 128; s > 0; s >>= 1) {
        if (tid < s) nz[tid] += nz[tid + s];
        __syncthreads();
    }
    if (tid == 0) g_is64 = (nz[0] == 0) ? 1 : 0;
}

__global__ void k_convert(const int* __restrict__ ei32) {
    int e = blockIdx.x * blockDim.x + threadIdx.x;
    if (e >= E_EDGES) return;
    if (g_is64) {
        g_src[e] = ei32[2 * e];
        g_dst[e] = ei32[2 * (E_EDGES + e)];
    } else {
        g_src[e] = ei32[e];
        g_dst[e] = ei32[E_EDGES + e];
    }
}

// ---------------------------------------------------------------------------
__global__ void k_zero_cnt() {
    int i = blockIdx.x * blockDim.x + threadIdx.x;
    if (i < N_NODES) g_cnt[i] = 0;
}

__global__ void k_count() {
    int e = blockIdx.x * blockDim.x + threadIdx.x;
    if (e < E_EDGES) atomicAdd(&g_cnt[g_dst[e]], 1);
}

// Single-block exclusive scan over g_cnt -> g_off, g_cur; also dis = rsqrt(deg)
__global__ __launch_bounds__(1024)
void k_scan() {
    __shared__ int sums[1024];
    const int tid = threadIdx.x;
    const int CH  = (N_NODES + 1023) / 1024;       // 98
    int beg = tid * CH;
    int end = beg + CH; if (end > N_NODES) end = N_NODES;
    if (beg > N_NODES) beg = N_NODES;

    int s = 0;
    for (int i = beg; i < end; i++) s += g_cnt[i];
    sums[tid] = s;
    __syncthreads();

    for (int off = 1; off < 1024; off <<= 1) {
        int v = (tid >= off) ? sums[tid - off] : 0;
        __syncthreads();
        sums[tid] += v;
        __syncthreads();
    }

    int run = (tid > 0) ? sums[tid - 1] : 0;       // exclusive prefix
    for (int i = beg; i < end; i++) {
        int c = g_cnt[i];
        g_off[i] = run;
        g_cur[i] = run;
        g_dis[i] = rsqrtf((float)(c + 1));         // deg includes self loop
        run += c;
    }
    if (tid == 0) g_off[N_NODES] = sums[1023];
}

__global__ void k_fill() {
    int e = blockIdx.x * blockDim.x + threadIdx.x;
    if (e >= E_EDGES) return;
    int p = atomicAdd(&g_cur[g_dst[e]], 1);
    g_esrc[p] = g_src[e];
}

// ---------------------------------------------------------------------------
// SGEMM: C[M,256] = dis .* (A[M,256] @ B[256,256]), row-major, fp32.
// 128x128 block tile, BK=16, 256 threads, 8x8 per-thread register tile.
// Epilogue scales row r by g_dis[r] (fused normalization).
__global__ __launch_bounds__(256)
void k_sgemm(const float* __restrict__ A, const float* __restrict__ B,
             float* __restrict__ C, int M) {
    const int BM = 128, BN = 128, BK = 16;
    __shared__ float As[BK][BM];
    __shared__ float Bs[BK][BN];

    int tid = threadIdx.x;
    int bm = blockIdx.y * BM;
    int bn = blockIdx.x * BN;

    int a_row  = tid >> 2;
    int a_col4 = tid & 3;
    int b_row  = tid >> 5;
    int b_col4 = tid & 31;

    int tx = tid & 15;
    int ty = tid >> 4;

    float acc[8][8];
#pragma unroll
    for (int i = 0; i < 8; i++)
#pragma unroll
        for (int j = 0; j < 8; j++) acc[i][j] = 0.0f;

    for (int k0 = 0; k0 < DD; k0 += BK) {
#pragma unroll
        for (int it = 0; it < 2; it++) {
            int r  = a_row + it * 64;
            int gr = bm + r;
            float4 v = make_float4(0.f, 0.f, 0.f, 0.f);
            if (gr < M)
                v = *(const float4*)(A + (size_t)gr * DD + k0 + a_col4 * 4);
            As[a_col4 * 4 + 0][r] = v.x;
            As[a_col4 * 4 + 1][r] = v.y;
            As[a_col4 * 4 + 2][r] = v.z;
            As[a_col4 * 4 + 3][r] = v.w;
        }
#pragma unroll
        for (int it = 0; it < 2; it++) {
            int r = b_row + it * 8;
            float4 v = *(const float4*)(B + (size_t)(k0 + r) * DD + bn + b_col4 * 4);
            *(float4*)(&Bs[r][b_col4 * 4]) = v;
        }
        __syncthreads();

#pragma unroll
        for (int k = 0; k < BK; k++) {
            float ra[8], rb[8];
#pragma unroll
            for (int i = 0; i < 8; i++) ra[i] = As[k][ty * 8 + i];
#pragma unroll
            for (int j = 0; j < 8; j++) rb[j] = Bs[k][tx * 8 + j];
#pragma unroll
            for (int i = 0; i < 8; i++)
#pragma unroll
                for (int j = 0; j < 8; j++)
                    acc[i][j] += ra[i] * rb[j];
        }
        __syncthreads();
    }

#pragma unroll
    for (int i = 0; i < 8; i++) {
        int gr = bm + ty * 8 + i;
        if (gr < M) {
            float s = g_dis[gr];
#pragma unroll
            for (int j = 0; j < 8; j += 4) {
                *(float4*)(C + (size_t)gr * DD + bn + tx * 8 + j) =
                    make_float4(s * acc[i][j],   s * acc[i][j+1],
                                s * acc[i][j+2], s * acc[i][j+3]);
            }
        }
    }
}

// ---------------------------------------------------------------------------
// Fused aggregate + bias + ELU, vectorized. 4 nodes per 256-thread block,
// 64 threads per node, one float4 column per thread.
//   out[n,:] = elu( dis[n] * ( xws[n,:] + sum_e xws[src_e,:] ) + b )
// where xws = dis .* (A@W) was produced by the GEMM epilogue. No atomics.
__global__ __launch_bounds__(256)
void k_agg(const float4* __restrict__ xws, const float* __restrict__ b,
           float* __restrict__ out) {
    int node = blockIdx.x * 4 + (threadIdx.x >> 6);
    if (node >= N_NODES) return;
    int t = threadIdx.x & 63;

    float4 acc = xws[(size_t)node * D4 + t];      // self-loop term (pre-scaled)

    int beg = g_off[node];
    int end = g_off[node + 1];

    int e = beg;
    for (; e + 4 <= end; e += 4) {
        int s0 = g_esrc[e + 0];
        int s1 = g_esrc[e + 1];
        int s2 = g_esrc[e + 2];
        int s3 = g_esrc[e + 3];
        float4 v0 = __ldg(&xws[(size_t)s0 * D4 + t]);
        float4 v1 = __ldg(&xws[(size_t)s1 * D4 + t]);
        float4 v2 = __ldg(&xws[(size_t)s2 * D4 + t]);
        float4 v3 = __ldg(&xws[(size_t)s3 * D4 + t]);
        acc.x += (v0.x + v1.x) + (v2.x + v3.x);
        acc.y += (v0.y + v1.y) + (v2.y + v3.y);
        acc.z += (v0.z + v1.z) + (v2.z + v3.z);
        acc.w += (v0.w + v1.w) + (v2.w + v3.w);
    }
    for (; e < end; e++) {
        int s0 = g_esrc[e];
        float4 v = __ldg(&xws[(size_t)s0 * D4 + t]);
        acc.x += v.x; acc.y += v.y; acc.z += v.z; acc.w += v.w;
    }

    float dn = g_dis[node];
    float4 bb = ((const float4*)b)[t];
    float4 r;
    r.x = dn * acc.x + bb.x;
    r.y = dn * acc.y + bb.y;
    r.z = dn * acc.z + bb.z;
    r.w = dn * acc.w + bb.w;
    r.x = r.x > 0.f ? r.x : expm1f(r.x);
    r.y = r.y > 0.f ? r.y : expm1f(r.y);
    r.z = r.z > 0.f ? r.z : expm1f(r.z);
    r.w = r.w > 0.f ? r.w : expm1f(r.w);
    ((float4*)out)[(size_t)node * D4 + t] = r;
}

// ---------------------------------------------------------------------------
extern "C" void kernel_launch(void* const* d_in, const int* in_sizes, int n_in,
                              void* d_out, int out_size) {
    const float* x   = (const float*)d_in[0];
    const int*   ei  = (const int*)d_in[1];    // int32 or int64 (auto-detected)
    const float* W1  = (const float*)d_in[2];
    const float* b1  = (const float*)d_in[3];
    const float* W2  = (const float*)d_in[4];
    const float* b2  = (const float*)d_in[5];
    float*       out = (float*)d_out;

    float* xw = nullptr; cudaGetSymbolAddress((void**)&xw, g_xw);
    float* h  = nullptr; cudaGetSymbolAddress((void**)&h,  g_h);

    const int T = 256;
    int grid_n   = (N_NODES + T - 1) / T;
    int grid_e   = (E_EDGES + T - 1) / T;
    int grid_agg = (N_NODES + 3) / 4;
    dim3 gemm_grid(DD / 128, (N_NODES + 127) / 128);

    // --- edge decode + CSR build + normalization (shared by both layers) ---
    k_detect  <<<1, 256>>>(ei);
    k_convert <<<grid_e, T>>>(ei);
    k_zero_cnt<<<grid_n, T>>>();
    k_count   <<<grid_e, T>>>();
    k_scan    <<<1, 1024>>>();
    k_fill    <<<grid_e, T>>>();

    // --- layer 1 ---
    k_sgemm<<<gemm_grid, T>>>(x, W1, xw, N_NODES);
    k_agg  <<<grid_agg, T>>>((const float4*)xw, b1, h);

    // --- layer 2 ---
    k_sgemm<<<gemm_grid, T>>>(h, W2, xw, N_NODES);
    k_agg  <<<grid_agg, T>>>((const float4*)xw, b2, out);
}

// round 6
// speedup vs baseline: 2.4991x; 1.2131x over previous
#include <cuda_runtime.h>
#include <cuda_bf16.h>
#include <cstdint>
#include <math.h>

// Problem constants (fixed by the reference)
#define N_NODES 100000
#define E_EDGES 3200000
#define DD 256           // feature dim
#define D4 (DD/4)        // 64 float4 per row

// ---------------- scratch (static device allocations; no cudaMalloc) -------
__device__ int   g_is64;
__device__ int   g_src [E_EDGES];
__device__ int   g_dst [E_EDGES];
__device__ int   g_cnt [N_NODES];
__device__ int   g_off [N_NODES + 1];
__device__ int   g_cur [N_NODES];
__device__ int   g_esrc[E_EDGES];
__device__ float g_dis [N_NODES];
__device__ float g_xw  [N_NODES * DD];            // dis .* (A @ W)  (per layer)
__device__ float g_h   [N_NODES * DD];            // layer-1 activations
__device__ __nv_bfloat16 g_wt_hi[DD * DD];        // W^T split, hi   [n][k]
__device__ __nv_bfloat16 g_wt_lo[DD * DD];        // W^T split, lo   [n][k]

// ---------------------------------------------------------------------------
// int32 vs int64 edge_index detection
__global__ void k_detect(const int* __restrict__ ei32) {
    __shared__ int nz[256];
    int tid = threadIdx.x;
    int acc = 0;
    for (int i = tid; i < 2048; i += 256)
        acc += (ei32[2 * i + 1] != 0) ? 1 : 0;
    nz[tid] = acc;
    __syncthreads();
    for (int s = 128; s > 0; s >>= 1) {
        if (tid < s) nz[tid] += nz[tid + s];
        __syncthreads();
    }
    if (tid == 0) g_is64 = (nz[0] == 0) ? 1 : 0;
}

__global__ void k_convert(const int* __restrict__ ei32) {
    int e = blockIdx.x * blockDim.x + threadIdx.x;
    if (e >= E_EDGES) return;
    if (g_is64) {
        g_src[e] = ei32[2 * e];
        g_dst[e] = ei32[2 * (E_EDGES + e)];
    } else {
        g_src[e] = ei32[e];
        g_dst[e] = ei32[E_EDGES + e];
    }
}

__global__ void k_zero_cnt() {
    int i = blockIdx.x * blockDim.x + threadIdx.x;
    if (i < N_NODES) g_cnt[i] = 0;
}

__global__ void k_count() {
    int e = blockIdx.x * blockDim.x + threadIdx.x;
    if (e < E_EDGES) atomicAdd(&g_cnt[g_dst[e]], 1);
}

__global__ __launch_bounds__(1024)
void k_scan() {
    __shared__ int sums[1024];
    const int tid = threadIdx.x;
    const int CH  = (N_NODES + 1023) / 1024;
    int beg = tid * CH;
    int end = beg + CH; if (end > N_NODES) end = N_NODES;
    if (beg > N_NODES) beg = N_NODES;

    int s = 0;
    for (int i = beg; i < end; i++) s += g_cnt[i];
    sums[tid] = s;
    __syncthreads();
    for (int off = 1; off < 1024; off <<= 1) {
        int v = (tid >= off) ? sums[tid - off] : 0;
        __syncthreads();
        sums[tid] += v;
        __syncthreads();
    }
    int run = (tid > 0) ? sums[tid - 1] : 0;
    for (int i = beg; i < end; i++) {
        int c = g_cnt[i];
        g_off[i] = run;
        g_cur[i] = run;
        g_dis[i] = rsqrtf((float)(c + 1));
        run += c;
    }
    if (tid == 0) g_off[N_NODES] = sums[1023];
}

__global__ void k_fill() {
    int e = blockIdx.x * blockDim.x + threadIdx.x;
    if (e >= E_EDGES) return;
    int p = atomicAdd(&g_cur[g_dst[e]], 1);
    g_esrc[p] = g_src[e];
}

// ---------------------------------------------------------------------------
// W^T split into bf16 hi/lo:  wt_hi[n][k] + wt_lo[n][k] ~= W[k][n]
__global__ void k_wsplit(const float* __restrict__ W) {
    int idx = blockIdx.x * blockDim.x + threadIdx.x;   // 65536
    int n = idx >> 8, k = idx & 255;
    float v = W[k * DD + n];
    __nv_bfloat16 hi = __float2bfloat16(v);
    float lo = v - __bfloat162float(hi);
    g_wt_hi[n * DD + k] = hi;
    g_wt_lo[n * DD + k] = __float2bfloat16(lo);
}

// ---------------------------------------------------------------------------
// mma.sync wrapper: m16n8k16 bf16 -> f32
__device__ __forceinline__ void mma_bf16(float* c, const uint32_t* a, const uint32_t* b) {
    asm volatile(
        "mma.sync.aligned.m16n8k16.row.col.f32.bf16.bf16.f32 "
        "{%0,%1,%2,%3}, {%4,%5,%6,%7}, {%8,%9}, {%0,%1,%2,%3};"
        : "+f"(c[0]), "+f"(c[1]), "+f"(c[2]), "+f"(c[3])
        : "r"(a[0]), "r"(a[1]), "r"(a[2]), "r"(a[3]), "r"(b[0]), "r"(b[1]));
}

// bf16-split GEMM via mma.sync: C[M,256] = dis .* (A[M,256] @ W[256,256])
// D = Ahi*Whi + Alo*Whi + Ahi*Wlo  (f32 accum).  CTA tile 128x128, BK=32,
// 8 warps (4 m x 2 n), warp tile 32x64. smem stride 40 bf16 (conflict-free).
#define SA 40
__global__ __launch_bounds__(256)
void k_gemm_mma(const float* __restrict__ A, float* __restrict__ C, int M) {
    __shared__ __nv_bfloat16 Ahi[128 * SA], Alo[128 * SA];
    __shared__ __nv_bfloat16 Bhi[128 * SA], Blo[128 * SA];

    const int tid  = threadIdx.x;
    const int wid  = tid >> 5;
    const int lane = tid & 31;
    const int wm   = wid & 3;          // 0..3 -> m
    const int wn   = wid >> 2;         // 0..1 -> n
    const int row0 = blockIdx.y * 128;
    const int bn   = blockIdx.x * 128;

    const int lq = lane >> 2;          // l/4 : 0..7
    const int lr = lane & 3;           // l%4 : 0..3

    float acc[2][8][4];
#pragma unroll
    for (int i = 0; i < 2; i++)
#pragma unroll
        for (int j = 0; j < 8; j++)
#pragma unroll
            for (int q = 0; q < 4; q++) acc[i][j][q] = 0.0f;

    for (int kb = 0; kb < DD; kb += 32) {
        // ---- stage A chunk: 128 rows x 32 cols fp32 -> bf16 hi/lo ----
#pragma unroll
        for (int it = 0; it < 4; it++) {
            int idx = it * 256 + tid;          // 1024 float4
            int r   = idx >> 3;
            int c4  = idx & 7;
            float4 v = make_float4(0.f, 0.f, 0.f, 0.f);
            if (row0 + r < M)
                v = *(const float4*)(A + (size_t)(row0 + r) * DD + kb + c4 * 4);
            __nv_bfloat16 h0 = __float2bfloat16(v.x), h1 = __float2bfloat16(v.y);
            __nv_bfloat16 h2 = __float2bfloat16(v.z), h3 = __float2bfloat16(v.w);
            __nv_bfloat16 l0 = __float2bfloat16(v.x - __bfloat162float(h0));
            __nv_bfloat16 l1 = __float2bfloat16(v.y - __bfloat162float(h1));
            __nv_bfloat16 l2 = __float2bfloat16(v.z - __bfloat162float(h2));
            __nv_bfloat16 l3 = __float2bfloat16(v.w - __bfloat162float(h3));
            __nv_bfloat162 hh01(h0, h1), hh23(h2, h3), ll01(l0, l1), ll23(l2, l3);
            int o = r * SA + c4 * 4;
            *(uint2*)(Ahi + o) = make_uint2(*(uint32_t*)&hh01, *(uint32_t*)&hh23);
            *(uint2*)(Alo + o) = make_uint2(*(uint32_t*)&ll01, *(uint32_t*)&ll23);
        }
        // ---- stage B chunk: 128 n-rows x 32 k-cols bf16 hi/lo ----
#pragma unroll
        for (int it = 0; it < 2; it++) {
            int idx = it * 256 + tid;          // 512 uint4
            int r   = idx >> 2;                // n row 0..127
            int u   = idx & 3;                 // 16B unit
            uint4 vh = *(const uint4*)(g_wt_hi + (size_t)(bn + r) * DD + kb + u * 8);
            uint4 vl = *(const uint4*)(g_wt_lo + (size_t)(bn + r) * DD + kb + u * 8);
            int o = r * SA + u * 8;
            *(uint2*)(Bhi + o)     = make_uint2(vh.x, vh.y);
            *(uint2*)(Bhi + o + 4) = make_uint2(vh.z, vh.w);
            *(uint2*)(Blo + o)     = make_uint2(vl.x, vl.y);
            *(uint2*)(Blo + o + 4) = make_uint2(vl.z, vl.w);
        }
        __syncthreads();

#pragma unroll
        for (int ks = 0; ks < 2; ks++) {
            const int k0 = ks * 16;
            // B fragments for this warp's 8 n-tiles
            uint32_t fbh[8][2], fbl[8][2];
#pragma unroll
            for (int j = 0; j < 8; j++) {
                int n0 = wn * 64 + j * 8;
                int o0 = (n0 + lq) * SA + k0 + lr * 2;
                fbh[j][0] = *(const uint32_t*)(Bhi + o0);
                fbh[j][1] = *(const uint32_t*)(Bhi + o0 + 8);
                fbl[j][0] = *(const uint32_t*)(Blo + o0);
                fbl[j][1] = *(const uint32_t*)(Blo + o0 + 8);
            }
#pragma unroll
            for (int i = 0; i < 2; i++) {
                int m0 = wm * 32 + i * 16;
                int oa = (m0 + lq) * SA + k0 + lr * 2;
                uint32_t fah[4], fal[4];
                fah[0] = *(const uint32_t*)(Ahi + oa);
                fah[1] = *(const uint32_t*)(Ahi + oa + 8 * SA);
                fah[2] = *(const uint32_t*)(Ahi + oa + 8);
                fah[3] = *(const uint32_t*)(Ahi + oa + 8 * SA + 8);
                fal[0] = *(const uint32_t*)(Alo + oa);
                fal[1] = *(const uint32_t*)(Alo + oa + 8 * SA);
                fal[2] = *(const uint32_t*)(Alo + oa + 8);
                fal[3] = *(const uint32_t*)(Alo + oa + 8 * SA + 8);
#pragma unroll
                for (int j = 0; j < 8; j++) {
                    mma_bf16(acc[i][j], fah, fbh[j]);   // hi*hi
                    mma_bf16(acc[i][j], fal, fbh[j]);   // lo*hi
                    mma_bf16(acc[i][j], fah, fbl[j]);   // hi*lo
                }
            }
        }
        __syncthreads();
    }

    // ---- epilogue: scale rows by dis, store fp32 ----
#pragma unroll
    for (int i = 0; i < 2; i++) {
        int r_lo = row0 + wm * 32 + i * 16 + lq;
        int r_hi = r_lo + 8;
        float d_lo = (r_lo < M) ? g_dis[r_lo] : 0.0f;
        float d_hi = (r_hi < M) ? g_dis[r_hi] : 0.0f;
#pragma unroll
        for (int j = 0; j < 8; j++) {
            int col = bn + wn * 64 + j * 8 + lr * 2;
            if (r_lo < M)
                *(float2*)(C + (size_t)r_lo * DD + col) =
                    make_float2(d_lo * acc[i][j][0], d_lo * acc[i][j][1]);
            if (r_hi < M)
                *(float2*)(C + (size_t)r_hi * DD + col) =
                    make_float2(d_hi * acc[i][j][2], d_hi * acc[i][j][3]);
        }
    }
}

// ---------------------------------------------------------------------------
// Fused aggregate + bias + ELU, vectorized (unchanged from R4).
__global__ __launch_bounds__(256)
void k_agg(const float4* __restrict__ xws, const float* __restrict__ b,
           float* __restrict__ out) {
    int node = blockIdx.x * 4 + (threadIdx.x >> 6);
    if (node >= N_NODES) return;
    int t = threadIdx.x & 63;

    float4 acc = xws[(size_t)node * D4 + t];

    int beg = g_off[node];
    int end = g_off[node + 1];

    int e = beg;
    for (; e + 4 <= end; e += 4) {
        int s0 = g_esrc[e + 0];
        int s1 = g_esrc[e + 1];
        int s2 = g_esrc[e + 2];
        int s3 = g_esrc[e + 3];
        float4 v0 = __ldg(&xws[(size_t)s0 * D4 + t]);
        float4 v1 = __ldg(&xws[(size_t)s1 * D4 + t]);
        float4 v2 = __ldg(&xws[(size_t)s2 * D4 + t]);
        float4 v3 = __ldg(&xws[(size_t)s3 * D4 + t]);
        acc.x += (v0.x + v1.x) + (v2.x + v3.x);
        acc.y += (v0.y + v1.y) + (v2.y + v3.y);
        acc.z += (v0.z + v1.z) + (v2.z + v3.z);
        acc.w += (v0.w + v1.w) + (v2.w + v3.w);
    }
    for (; e < end; e++) {
        int s0 = g_esrc[e];
        float4 v = __ldg(&xws[(size_t)s0 * D4 + t]);
        acc.x += v.x; acc.y += v.y; acc.z += v.z; acc.w += v.w;
    }

    float dn = g_dis[node];
    float4 bb = ((const float4*)b)[t];
    float4 r;
    r.x = dn * acc.x + bb.x;
    r.y = dn * acc.y + bb.y;
    r.z = dn * acc.z + bb.z;
    r.w = dn * acc.w + bb.w;
    r.x = r.x > 0.f ? r.x : expm1f(r.x);
    r.y = r.y > 0.f ? r.y : expm1f(r.y);
    r.z = r.z > 0.f ? r.z : expm1f(r.z);
    r.w = r.w > 0.f ? r.w : expm1f(r.w);
    ((float4*)out)[(size_t)node * D4 + t] = r;
}

// ---------------------------------------------------------------------------
extern "C" void kernel_launch(void* const* d_in, const int* in_sizes, int n_in,
                              void* d_out, int out_size) {
    const float* x   = (const float*)d_in[0];
    const int*   ei  = (const int*)d_in[1];
    const float* W1  = (const float*)d_in[2];
    const float* b1  = (const float*)d_in[3];
    const float* W2  = (const float*)d_in[4];
    const float* b2  = (const float*)d_in[5];
    float*       out = (float*)d_out;

    float* xw = nullptr; cudaGetSymbolAddress((void**)&xw, g_xw);
    float* h  = nullptr; cudaGetSymbolAddress((void**)&h,  g_h);

    const int T = 256;
    int grid_n   = (N_NODES + T - 1) / T;
    int grid_e   = (E_EDGES + T - 1) / T;
    int grid_agg = (N_NODES + 3) / 4;
    dim3 gemm_grid(DD / 128, (N_NODES + 127) / 128);

    // --- edge decode + CSR build + normalization ---
    k_detect  <<<1, 256>>>(ei);
    k_convert <<<grid_e, T>>>(ei);
    k_zero_cnt<<<grid_n, T>>>();
    k_count   <<<grid_e, T>>>();
    k_scan    <<<1, 1024>>>();
    k_fill    <<<grid_e, T>>>();

    // --- layer 1 ---
    k_wsplit  <<<DD, DD>>>(W1);
    k_gemm_mma<<<gemm_grid, T>>>(x, xw, N_NODES);
    k_agg     <<<grid_agg, T>>>((const float4*)xw, b1, h);

    // --- layer 2 ---
    k_wsplit  <<<DD, DD>>>(W2);
    k_gemm_mma<<<gemm_grid, T>>>(h, xw, N_NODES);
    k_agg     <<<grid_agg, T>>>((const float4*)xw, b2, out);
}

// round 7
// speedup vs baseline: 3.0093x; 1.2042x over previous
#include <cuda_runtime.h>
#include <cuda_bf16.h>
#include <cuda_fp16.h>
#include <cstdint>
#include <math.h>

// Problem constants (fixed by the reference)
#define N_NODES 100000
#define E_EDGES 3200000
#define DD 256           // feature dim

// ---------------- scratch (static device allocations; no cudaMalloc) -------
__device__ int    g_is64;
__device__ int    g_src [E_EDGES];
__device__ int    g_dst [E_EDGES];
__device__ int    g_cnt [N_NODES];
__device__ int    g_off [N_NODES + 1];
__device__ int    g_cur [N_NODES];
__device__ int    g_esrc[E_EDGES];
__device__ float  g_dis [N_NODES];
__device__ __half g_xw16[N_NODES * DD];           // A @ W in fp16 (per layer)
__device__ float  g_h   [N_NODES * DD];           // layer-1 activations
__device__ __nv_bfloat16 g_wt_hi[DD * DD];        // W^T split, hi   [n][k]
__device__ __nv_bfloat16 g_wt_lo[DD * DD];        // W^T split, lo   [n][k]

// ---------------------------------------------------------------------------
// int32 vs int64 edge_index detection
__global__ void k_detect(const int* __restrict__ ei32) {
    __shared__ int nz[256];
    int tid = threadIdx.x;
    int acc = 0;
    for (int i = tid; i < 2048; i += 256)
        acc += (ei32[2 * i + 1] != 0) ? 1 : 0;
    nz[tid] = acc;
    __syncthreads();
    for (int s = 128; s > 0; s >>= 1) {
        if (tid < s) nz[tid] += nz[tid + s];
        __syncthreads();
    }
    if (tid == 0) g_is64 = (nz[0] == 0) ? 1 : 0;
}

__global__ void k_zero_cnt() {
    int i = blockIdx.x * blockDim.x + threadIdx.x;
    if (i < N_NODES) g_cnt[i] = 0;
}

// decode + histogram in one pass
__global__ void k_convert_count(const int* __restrict__ ei32) {
    int e = blockIdx.x * blockDim.x + threadIdx.x;
    if (e >= E_EDGES) return;
    int s, t;
    if (g_is64) {
        s = ei32[2 * e];
        t = ei32[2 * (E_EDGES + e)];
    } else {
        s = ei32[e];
        t = ei32[E_EDGES + e];
    }
    g_src[e] = s;
    g_dst[e] = t;
    atomicAdd(&g_cnt[t], 1);
}

__global__ __launch_bounds__(1024)
void k_scan() {
    __shared__ int sums[1024];
    const int tid = threadIdx.x;
    const int CH  = (N_NODES + 1023) / 1024;
    int beg = tid * CH;
    int end = beg + CH; if (end > N_NODES) end = N_NODES;
    if (beg > N_NODES) beg = N_NODES;

    int s = 0;
    for (int i = beg; i < end; i++) s += g_cnt[i];
    sums[tid] = s;
    __syncthreads();
    for (int off = 1; off < 1024; off <<= 1) {
        int v = (tid >= off) ? sums[tid - off] : 0;
        __syncthreads();
        sums[tid] += v;
        __syncthreads();
    }
    int run = (tid > 0) ? sums[tid - 1] : 0;
    for (int i = beg; i < end; i++) {
        int c = g_cnt[i];
        g_off[i] = run;
        g_cur[i] = run;
        g_dis[i] = rsqrtf((float)(c + 1));
        run += c;
    }
    if (tid == 0) g_off[N_NODES] = sums[1023];
}

__global__ void k_fill() {
    int e = blockIdx.x * blockDim.x + threadIdx.x;
    if (e >= E_EDGES) return;
    int p = atomicAdd(&g_cur[g_dst[e]], 1);
    g_esrc[p] = g_src[e];
}

// ---------------------------------------------------------------------------
// W^T split into bf16 hi/lo:  wt_hi[n][k] + wt_lo[n][k] ~= W[k][n]
__global__ void k_wsplit(const float* __restrict__ W) {
    int idx = blockIdx.x * blockDim.x + threadIdx.x;   // 65536
    int n = idx >> 8, k = idx & 255;
    float v = W[k * DD + n];
    __nv_bfloat16 hi = __float2bfloat16(v);
    float lo = v - __bfloat162float(hi);
    g_wt_hi[n * DD + k] = hi;
    g_wt_lo[n * DD + k] = __float2bfloat16(lo);
}

// ---------------------------------------------------------------------------
// mma.sync wrapper: m16n8k16 bf16 -> f32
__device__ __forceinline__ void mma_bf16(float* c, const uint32_t* a, const uint32_t* b) {
    asm volatile(
        "mma.sync.aligned.m16n8k16.row.col.f32.bf16.bf16.f32 "
        "{%0,%1,%2,%3}, {%4,%5,%6,%7}, {%8,%9}, {%0,%1,%2,%3};"
        : "+f"(c[0]), "+f"(c[1]), "+f"(c[2]), "+f"(c[3])
        : "r"(a[0]), "r"(a[1]), "r"(a[2]), "r"(a[3]), "r"(b[0]), "r"(b[1]));
}

// bf16-split GEMM via mma.sync: C16[M,256] = fp16( A[M,256] @ W[256,256] )
// D = Ahi*Whi + Alo*Whi + Ahi*Wlo  (f32 accum).  CTA tile 128x128, BK=32,
// 8 warps (4 m x 2 n), warp tile 32x64. smem stride 40 bf16 (conflict-free).
#define SA 40
__global__ __launch_bounds__(256)
void k_gemm_mma(const float* __restrict__ A, __half* __restrict__ C, int M) {
    __shared__ __nv_bfloat16 Ahi[128 * SA], Alo[128 * SA];
    __shared__ __nv_bfloat16 Bhi[128 * SA], Blo[128 * SA];

    const int tid  = threadIdx.x;
    const int wid  = tid >> 5;
    const int lane = tid & 31;
    const int wm   = wid & 3;          // 0..3 -> m
    const int wn   = wid >> 2;         // 0..1 -> n
    const int row0 = blockIdx.y * 128;
    const int bn   = blockIdx.x * 128;

    const int lq = lane >> 2;          // 0..7
    const int lr = lane & 3;           // 0..3

    float acc[2][8][4];
#pragma unroll
    for (int i = 0; i < 2; i++)
#pragma unroll
        for (int j = 0; j < 8; j++)
#pragma unroll
            for (int q = 0; q < 4; q++) acc[i][j][q] = 0.0f;

    for (int kb = 0; kb < DD; kb += 32) {
        // ---- stage A chunk: 128 rows x 32 cols fp32 -> bf16 hi/lo ----
#pragma unroll
        for (int it = 0; it < 4; it++) {
            int idx = it * 256 + tid;          // 1024 float4
            int r   = idx >> 3;
            int c4  = idx & 7;
            float4 v = make_float4(0.f, 0.f, 0.f, 0.f);
            if (row0 + r < M)
                v = *(const float4*)(A + (size_t)(row0 + r) * DD + kb + c4 * 4);
            __nv_bfloat16 h0 = __float2bfloat16(v.x), h1 = __float2bfloat16(v.y);
            __nv_bfloat16 h2 = __float2bfloat16(v.z), h3 = __float2bfloat16(v.w);
            __nv_bfloat16 l0 = __float2bfloat16(v.x - __bfloat162float(h0));
            __nv_bfloat16 l1 = __float2bfloat16(v.y - __bfloat162float(h1));
            __nv_bfloat16 l2 = __float2bfloat16(v.z - __bfloat162float(h2));
            __nv_bfloat16 l3 = __float2bfloat16(v.w - __bfloat162float(h3));
            __nv_bfloat162 hh01(h0, h1), hh23(h2, h3), ll01(l0, l1), ll23(l2, l3);
            int o = r * SA + c4 * 4;
            *(uint2*)(Ahi + o) = make_uint2(*(uint32_t*)&hh01, *(uint32_t*)&hh23);
            *(uint2*)(Alo + o) = make_uint2(*(uint32_t*)&ll01, *(uint32_t*)&ll23);
        }
        // ---- stage B chunk: 128 n-rows x 32 k-cols bf16 hi/lo ----
#pragma unroll
        for (int it = 0; it < 2; it++) {
            int idx = it * 256 + tid;          // 512 uint4
            int r   = idx >> 2;
            int u   = idx & 3;
            uint4 vh = *(const uint4*)(g_wt_hi + (size_t)(bn + r) * DD + kb + u * 8);
            uint4 vl = *(const uint4*)(g_wt_lo + (size_t)(bn + r) * DD + kb + u * 8);
            int o = r * SA + u * 8;
            *(uint2*)(Bhi + o)     = make_uint2(vh.x, vh.y);
            *(uint2*)(Bhi + o + 4) = make_uint2(vh.z, vh.w);
            *(uint2*)(Blo + o)     = make_uint2(vl.x, vl.y);
            *(uint2*)(Blo + o + 4) = make_uint2(vl.z, vl.w);
        }
        __syncthreads();

#pragma unroll
        for (int ks = 0; ks < 2; ks++) {
            const int k0 = ks * 16;
            uint32_t fbh[8][2], fbl[8][2];
#pragma unroll
            for (int j = 0; j < 8; j++) {
                int n0 = wn * 64 + j * 8;
                int o0 = (n0 + lq) * SA + k0 + lr * 2;
                fbh[j][0] = *(const uint32_t*)(Bhi + o0);
                fbh[j][1] = *(const uint32_t*)(Bhi + o0 + 8);
                fbl[j][0] = *(const uint32_t*)(Blo + o0);
                fbl[j][1] = *(const uint32_t*)(Blo + o0 + 8);
            }
#pragma unroll
            for (int i = 0; i < 2; i++) {
                int m0 = wm * 32 + i * 16;
                int oa = (m0 + lq) * SA + k0 + lr * 2;
                uint32_t fah[4], fal[4];
                fah[0] = *(const uint32_t*)(Ahi + oa);
                fah[1] = *(const uint32_t*)(Ahi + oa + 8 * SA);
                fah[2] = *(const uint32_t*)(Ahi + oa + 8);
                fah[3] = *(const uint32_t*)(Ahi + oa + 8 * SA + 8);
                fal[0] = *(const uint32_t*)(Alo + oa);
                fal[1] = *(const uint32_t*)(Alo + oa + 8 * SA);
                fal[2] = *(const uint32_t*)(Alo + oa + 8);
                fal[3] = *(const uint32_t*)(Alo + oa + 8 * SA + 8);
#pragma unroll
                for (int j = 0; j < 8; j++) {
                    mma_bf16(acc[i][j], fah, fbh[j]);   // hi*hi
                    mma_bf16(acc[i][j], fal, fbh[j]);   // lo*hi
                    mma_bf16(acc[i][j], fah, fbl[j]);   // hi*lo
                }
            }
        }
        __syncthreads();
    }

    // ---- epilogue: store fp16 (un-scaled; dis applied in aggregation) ----
#pragma unroll
    for (int i = 0; i < 2; i++) {
        int r_lo = row0 + wm * 32 + i * 16 + lq;
        int r_hi = r_lo + 8;
#pragma unroll
        for (int j = 0; j < 8; j++) {
            int col = bn + wn * 64 + j * 8 + lr * 2;
            if (r_lo < M) {
                __half2 p = __floats2half2_rn(acc[i][j][0], acc[i][j][1]);
                *(uint32_t*)(C + (size_t)r_lo * DD + col) = *(uint32_t*)&p;
            }
            if (r_hi < M) {
                __half2 p = __floats2half2_rn(acc[i][j][2], acc[i][j][3]);
                *(uint32_t*)(C + (size_t)r_hi * DD + col) = *(uint32_t*)&p;
            }
        }
    }
}

// ---------------------------------------------------------------------------
// Fused aggregate + norm + bias + ELU from fp16 features.
// 8 nodes per 256-thread block, 32 threads/node, one uint4 (8 halfs) per thread.
//   out[n,:] = elu( dn * ( dn*xw[n,:] + sum_e dis[src_e]*xw[src_e,:] ) + b )
__global__ __launch_bounds__(256)
void k_agg(const __half* __restrict__ xw16, const float* __restrict__ b,
           float* __restrict__ out) {
    int node = blockIdx.x * 8 + (threadIdx.x >> 5);
    if (node >= N_NODES) return;
    int t = threadIdx.x & 31;                       // uint4 index within row

    const uint4* X = (const uint4*)xw16;            // 32 uint4 per row

    float dn = g_dis[node];
    float acc[8];
    {
        uint4 v = __ldg(&X[(size_t)node * 32 + t]);
        const __half2* h2 = (const __half2*)&v;
#pragma unroll
        for (int q = 0; q < 4; q++) {
            float2 f = __half22float2(h2[q]);
            acc[2 * q]     = dn * f.x;
            acc[2 * q + 1] = dn * f.y;
        }
    }

    int beg = g_off[node];
    int end = g_off[node + 1];

    int e = beg;
    for (; e + 4 <= end; e += 4) {
        int s0 = g_esrc[e + 0];
        int s1 = g_esrc[e + 1];
        int s2 = g_esrc[e + 2];
        int s3 = g_esrc[e + 3];
        float w0 = g_dis[s0], w1 = g_dis[s1], w2 = g_dis[s2], w3 = g_dis[s3];
        uint4 v0 = __ldg(&X[(size_t)s0 * 32 + t]);
        uint4 v1 = __ldg(&X[(size_t)s1 * 32 + t]);
        uint4 v2 = __ldg(&X[(size_t)s2 * 32 + t]);
        uint4 v3 = __ldg(&X[(size_t)s3 * 32 + t]);
        const __half2* a0 = (const __half2*)&v0;
        const __half2* a1 = (const __half2*)&v1;
        const __half2* a2 = (const __half2*)&v2;
        const __half2* a3 = (const __half2*)&v3;
#pragma unroll
        for (int q = 0; q < 4; q++) {
            float2 f0 = __half22float2(a0[q]);
            float2 f1 = __half22float2(a1[q]);
            float2 f2 = __half22float2(a2[q]);
            float2 f3 = __half22float2(a3[q]);
            acc[2 * q]     += w0 * f0.x + w1 * f1.x + w2 * f2.x + w3 * f3.x;
            acc[2 * q + 1] += w0 * f0.y + w1 * f1.y + w2 * f2.y + w3 * f3.y;
        }
    }
    for (; e < end; e++) {
        int s0 = g_esrc[e];
        float w0 = g_dis[s0];
        uint4 v0 = __ldg(&X[(size_t)s0 * 32 + t]);
        const __half2* a0 = (const __half2*)&v0;
#pragma unroll
        for (int q = 0; q < 4; q++) {
            float2 f0 = __half22float2(a0[q]);
            acc[2 * q]     += w0 * f0.x;
            acc[2 * q + 1] += w0 * f0.y;
        }
    }

    float4 b0 = *(const float4*)(b + t * 8);
    float4 b1 = *(const float4*)(b + t * 8 + 4);
    float r[8];
    r[0] = dn * acc[0] + b0.x;  r[1] = dn * acc[1] + b0.y;
    r[2] = dn * acc[2] + b0.z;  r[3] = dn * acc[3] + b0.w;
    r[4] = dn * acc[4] + b1.x;  r[5] = dn * acc[5] + b1.y;
    r[6] = dn * acc[6] + b1.z;  r[7] = dn * acc[7] + b1.w;
#pragma unroll
    for (int q = 0; q < 8; q++)
        r[q] = r[q] > 0.f ? r[q] : expm1f(r[q]);

    float* O = out + (size_t)node * DD + t * 8;
    *(float4*)(O)     = make_float4(r[0], r[1], r[2], r[3]);
    *(float4*)(O + 4) = make_float4(r[4], r[5], r[6], r[7]);
}

// ---------------------------------------------------------------------------
extern "C" void kernel_launch(void* const* d_in, const int* in_sizes, int n_in,
                              void* d_out, int out_size) {
    const float* x   = (const float*)d_in[0];
    const int*   ei  = (const int*)d_in[1];
    const float* W1  = (const float*)d_in[2];
    const float* b1  = (const float*)d_in[3];
    const float* W2  = (const float*)d_in[4];
    const float* b2  = (const float*)d_in[5];
    float*       out = (float*)d_out;

    __half* xw16 = nullptr; cudaGetSymbolAddress((void**)&xw16, g_xw16);
    float*  h    = nullptr; cudaGetSymbolAddress((void**)&h,    g_h);

    const int T = 256;
    int grid_n   = (N_NODES + T - 1) / T;
    int grid_e   = (E_EDGES + T - 1) / T;
    int grid_agg = (N_NODES + 7) / 8;
    dim3 gemm_grid(DD / 128, (N_NODES + 127) / 128);

    // Side stream + events: overlap layer-1 GEMM with CSR build during capture.
    cudaStream_t s2;
    cudaStreamCreate(&s2);
    cudaEvent_t evFork, evJoin;
    cudaEventCreateWithFlags(&evFork, cudaEventDisableTiming);
    cudaEventCreateWithFlags(&evJoin, cudaEventDisableTiming);

    // fork: layer-1 GEMM path (independent of CSR/normalization)
    cudaEventRecord(evFork, 0);
    cudaStreamWaitEvent(s2, evFork, 0);
    k_wsplit  <<<DD, DD, 0, s2>>>(W1);
    k_gemm_mma<<<gemm_grid, T, 0, s2>>>(x, xw16, N_NODES);
    cudaEventRecord(evJoin, s2);

    // main stream: edge decode + CSR build + normalization
    k_detect       <<<1, 256>>>(ei);
    k_zero_cnt     <<<grid_n, T>>>();
    k_convert_count<<<grid_e, T>>>(ei);
    k_scan         <<<1, 1024>>>();
    k_fill         <<<grid_e, T>>>();

    // join, then layer-1 aggregation
    cudaStreamWaitEvent(0, evJoin, 0);
    k_agg<<<grid_agg, T>>>((const __half*)xw16, b1, h);

    // --- layer 2 (serial) ---
    k_wsplit  <<<DD, DD>>>(W2);
    k_gemm_mma<<<gemm_grid, T>>>(h, xw16, N_NODES);
    k_agg     <<<grid_agg, T>>>((const __half*)xw16, b2, out);

    cudaStreamDestroy(s2);
    cudaEventDestroy(evFork);
    cudaEventDestroy(evJoin);
}

// round 8
// speedup vs baseline: 3.5783x; 1.1891x over previous
#include <cuda_runtime.h>
#include <cuda_fp16.h>
#include <cstdint>
#include <math.h>

// Problem constants (fixed by the reference)
#define N_NODES 100000
#define E_EDGES 3200000
#define DD 256           // feature dim

// ---------------- scratch (static device allocations; no cudaMalloc) -------
__device__ int    g_is64;
__device__ int    g_src [E_EDGES];
__device__ int    g_dst [E_EDGES];
__device__ int    g_cnt [N_NODES];
__device__ int    g_off [N_NODES + 1];
__device__ int    g_cur [N_NODES];
__device__ int    g_esrc[E_EDGES];
__device__ float  g_dis [N_NODES];
__device__ __half g_x16 [N_NODES * DD];           // input features, fp16
__device__ __half g_xw16[N_NODES * DD];           // A @ W in fp16 (per layer)
__device__ __half g_h16 [N_NODES * DD];           // layer-1 activations, fp16
__device__ __half g_w1hi[DD * DD], g_w1lo[DD * DD];  // W1^T split [n][k]
__device__ __half g_w2hi[DD * DD], g_w2lo[DD * DD];  // W2^T split [n][k]

// ---------------------------------------------------------------------------
__global__ void k_detect(const int* __restrict__ ei32) {
    __shared__ int nz[256];
    int tid = threadIdx.x;
    int acc = 0;
    for (int i = tid; i < 2048; i += 256)
        acc += (ei32[2 * i + 1] != 0) ? 1 : 0;
    nz[tid] = acc;
    __syncthreads();
    for (int s = 128; s > 0; s >>= 1) {
        if (tid < s) nz[tid] += nz[tid + s];
        __syncthreads();
    }
    if (tid == 0) g_is64 = (nz[0] == 0) ? 1 : 0;
}

__global__ void k_zero_cnt() {
    int i = blockIdx.x * blockDim.x + threadIdx.x;
    if (i < N_NODES) g_cnt[i] = 0;
}

// decode + histogram in one pass
__global__ void k_convert_count(const int* __restrict__ ei32) {
    int e = blockIdx.x * blockDim.x + threadIdx.x;
    if (e >= E_EDGES) return;
    int s, t;
    if (g_is64) {
        s = ei32[2 * e];
        t = ei32[2 * (E_EDGES + e)];
    } else {
        s = ei32[e];
        t = ei32[E_EDGES + e];
    }
    g_src[e] = s;
    g_dst[e] = t;
    atomicAdd(&g_cnt[t], 1);
}

__global__ __launch_bounds__(1024)
void k_scan() {
    __shared__ int sums[1024];
    const int tid = threadIdx.x;
    const int CH  = (N_NODES + 1023) / 1024;
    int beg = tid * CH;
    int end = beg + CH; if (end > N_NODES) end = N_NODES;
    if (beg > N_NODES) beg = N_NODES;

    int s = 0;
    for (int i = beg; i < end; i++) s += g_cnt[i];
    sums[tid] = s;
    __syncthreads();
    for (int off = 1; off < 1024; off <<= 1) {
        int v = (tid >= off) ? sums[tid - off] : 0;
        __syncthreads();
        sums[tid] += v;
        __syncthreads();
    }
    int run = (tid > 0) ? sums[tid - 1] : 0;
    for (int i = beg; i < end; i++) {
        int c = g_cnt[i];
        g_off[i] = run;
        g_cur[i] = run;
        g_dis[i] = rsqrtf((float)(c + 1));
        run += c;
    }
    if (tid == 0) g_off[N_NODES] = sums[1023];
}

__global__ void k_fill() {
    int e = blockIdx.x * blockDim.x + threadIdx.x;
    if (e >= E_EDGES) return;
    int p = atomicAdd(&g_cur[g_dst[e]], 1);
    g_esrc[p] = g_src[e];
}

// ---------------------------------------------------------------------------
// x (fp32) -> fp16 copy; each thread handles 8 elements
__global__ void k_cvt_x(const float* __restrict__ x) {
    int idx = blockIdx.x * blockDim.x + threadIdx.x;   // over N*DD/8
    if (idx >= N_NODES * DD / 8) return;
    float4 a = *(const float4*)(x + idx * 8);
    float4 b = *(const float4*)(x + idx * 8 + 4);
    __half2 p0 = __floats2half2_rn(a.x, a.y);
    __half2 p1 = __floats2half2_rn(a.z, a.w);
    __half2 p2 = __floats2half2_rn(b.x, b.y);
    __half2 p3 = __floats2half2_rn(b.z, b.w);
    uint4 v = make_uint4(*(uint32_t*)&p0, *(uint32_t*)&p1,
                         *(uint32_t*)&p2, *(uint32_t*)&p3);
    *(uint4*)(g_x16 + idx * 8) = v;
}

// W^T split into fp16 hi/lo:  whi[n][k] + wlo[n][k] ~= W[k][n]
__global__ void k_wsplit(const float* __restrict__ W,
                         __half* __restrict__ whi, __half* __restrict__ wlo) {
    int idx = blockIdx.x * blockDim.x + threadIdx.x;   // 65536
    int n = idx >> 8, k = idx & 255;
    float v = W[k * DD + n];
    __half hi = __float2half_rn(v);
    float lo = v - __half2float(hi);
    whi[n * DD + k] = hi;
    wlo[n * DD + k] = __float2half_rn(lo);
}

// ---------------------------------------------------------------------------
// mma.sync wrapper: m16n8k16 fp16 -> f32
__device__ __forceinline__ void mma_f16(float* c, const uint32_t* a, const uint32_t* b) {
    asm volatile(
        "mma.sync.aligned.m16n8k16.row.col.f32.f16.f16.f32 "
        "{%0,%1,%2,%3}, {%4,%5,%6,%7}, {%8,%9}, {%0,%1,%2,%3};"
        : "+f"(c[0]), "+f"(c[1]), "+f"(c[2]), "+f"(c[3])
        : "r"(a[0]), "r"(a[1]), "r"(a[2]), "r"(a[3]), "r"(b[0]), "r"(b[1]));
}

// fp16 GEMM via mma.sync: C16[M,256] = fp16( A16[M,256] @ W[256,256] )
// D = A*Whi + A*Wlo  (f32 accum).  CTA tile 128x128, BK=32, 8 warps (4m x 2n),
// warp tile 32x64. smem stride 40 halfs (20 words, odd -> conflict-free).
#define SA 40
__global__ __launch_bounds__(256)
void k_gemm_mma(const __half* __restrict__ A, __half* __restrict__ C,
                const __half* __restrict__ Whi, const __half* __restrict__ Wlo,
                int M) {
    __shared__ __half Af [128 * SA];
    __shared__ __half Bhi[128 * SA], Blo[128 * SA];

    const int tid  = threadIdx.x;
    const int wid  = tid >> 5;
    const int lane = tid & 31;
    const int wm   = wid & 3;
    const int wn   = wid >> 2;
    const int row0 = blockIdx.y * 128;
    const int bn   = blockIdx.x * 128;

    const int lq = lane >> 2;          // 0..7
    const int lr = lane & 3;           // 0..3

    float acc[2][8][4];
#pragma unroll
    for (int i = 0; i < 2; i++)
#pragma unroll
        for (int j = 0; j < 8; j++)
#pragma unroll
            for (int q = 0; q < 4; q++) acc[i][j][q] = 0.0f;

    for (int kb = 0; kb < DD; kb += 32) {
        // ---- stage A chunk: 128 rows x 32 halfs (64B/row) ----
#pragma unroll
        for (int it = 0; it < 2; it++) {
            int idx = it * 256 + tid;          // 512 uint4
            int r   = idx >> 2;                // row 0..127
            int u   = idx & 3;                 // 16B unit
            uint4 v = make_uint4(0u, 0u, 0u, 0u);
            if (row0 + r < M)
                v = *(const uint4*)(A + (size_t)(row0 + r) * DD + kb + u * 8);
            *(uint4*)(Af + r * SA + u * 8) = v;
        }
        // ---- stage B chunk: 128 n-rows x 32 k-halfs, hi + lo ----
#pragma unroll
        for (int it = 0; it < 2; it++) {
            int idx = it * 256 + tid;
            int r   = idx >> 2;
            int u   = idx & 3;
            uint4 vh = *(const uint4*)(Whi + (size_t)(bn + r) * DD + kb + u * 8);
            uint4 vl = *(const uint4*)(Wlo + (size_t)(bn + r) * DD + kb + u * 8);
            *(uint4*)(Bhi + r * SA + u * 8) = vh;
            *(uint4*)(Blo + r * SA + u * 8) = vl;
        }
        __syncthreads();

#pragma unroll
        for (int ks = 0; ks < 2; ks++) {
            const int k0 = ks * 16;
            uint32_t fbh[8][2], fbl[8][2];
#pragma unroll
            for (int j = 0; j < 8; j++) {
                int n0 = wn * 64 + j * 8;
                int o0 = (n0 + lq) * SA + k0 + lr * 2;
                fbh[j][0] = *(const uint32_t*)(Bhi + o0);
                fbh[j][1] = *(const uint32_t*)(Bhi + o0 + 8);
                fbl[j][0] = *(const uint32_t*)(Blo + o0);
                fbl[j][1] = *(const uint32_t*)(Blo + o0 + 8);
            }
#pragma unroll
            for (int i = 0; i < 2; i++) {
                int m0 = wm * 32 + i * 16;
                int oa = (m0 + lq) * SA + k0 + lr * 2;
                uint32_t fa[4];
                fa[0] = *(const uint32_t*)(Af + oa);
                fa[1] = *(const uint32_t*)(Af + oa + 8 * SA);
                fa[2] = *(const uint32_t*)(Af + oa + 8);
                fa[3] = *(const uint32_t*)(Af + oa + 8 * SA + 8);
#pragma unroll
                for (int j = 0; j < 8; j++) {
                    mma_f16(acc[i][j], fa, fbh[j]);   // A * Whi
                    mma_f16(acc[i][j], fa, fbl[j]);   // A * Wlo
                }
            }
        }
        __syncthreads();
    }

    // ---- epilogue: store fp16 (un-scaled; dis applied in aggregation) ----
#pragma unroll
    for (int i = 0; i < 2; i++) {
        int r_lo = row0 + wm * 32 + i * 16 + lq;
        int r_hi = r_lo + 8;
#pragma unroll
        for (int j = 0; j < 8; j++) {
            int col = bn + wn * 64 + j * 8 + lr * 2;
            if (r_lo < M) {
                __half2 p = __floats2half2_rn(acc[i][j][0], acc[i][j][1]);
                *(uint32_t*)(C + (size_t)r_lo * DD + col) = *(uint32_t*)&p;
            }
            if (r_hi < M) {
                __half2 p = __floats2half2_rn(acc[i][j][2], acc[i][j][3]);
                *(uint32_t*)(C + (size_t)r_hi * DD + col) = *(uint32_t*)&p;
            }
        }
    }
}

// ---------------------------------------------------------------------------
// Fused aggregate + norm + bias + ELU from fp16 features.
// 8 nodes per 256-thread block, 32 threads/node, one uint4 (8 halfs) per thread.
//   out[n,:] = elu( dn * ( dn*xw[n,:] + sum_e dis[src_e]*xw[src_e,:] ) + b )
// OUT16: store fp16 (layer 1) vs fp32 (final output).
template <bool OUT16>
__global__ __launch_bounds__(256)
void k_agg(const __half* __restrict__ xw16, const float* __restrict__ b,
           void* __restrict__ outp) {
    int node = blockIdx.x * 8 + (threadIdx.x >> 5);
    if (node >= N_NODES) return;
    int t = threadIdx.x & 31;

    const uint4* X = (const uint4*)xw16;            // 32 uint4 per row

    float dn = g_dis[node];
    float acc[8];
    {
        uint4 v = __ldg(&X[(size_t)node * 32 + t]);
        const __half2* h2 = (const __half2*)&v;
#pragma unroll
        for (int q = 0; q < 4; q++) {
            float2 f = __half22float2(h2[q]);
            acc[2 * q]     = dn * f.x;
            acc[2 * q + 1] = dn * f.y;
        }
    }

    int beg = g_off[node];
    int end = g_off[node + 1];

    int e = beg;
    for (; e + 4 <= end; e += 4) {
        int s0 = g_esrc[e + 0];
        int s1 = g_esrc[e + 1];
        int s2 = g_esrc[e + 2];
        int s3 = g_esrc[e + 3];
        float w0 = g_dis[s0], w1 = g_dis[s1], w2 = g_dis[s2], w3 = g_dis[s3];
        uint4 v0 = __ldg(&X[(size_t)s0 * 32 + t]);
        uint4 v1 = __ldg(&X[(size_t)s1 * 32 + t]);
        uint4 v2 = __ldg(&X[(size_t)s2 * 32 + t]);
        uint4 v3 = __ldg(&X[(size_t)s3 * 32 + t]);
        const __half2* a0 = (const __half2*)&v0;
        const __half2* a1 = (const __half2*)&v1;
        const __half2* a2 = (const __half2*)&v2;
        const __half2* a3 = (const __half2*)&v3;
#pragma unroll
        for (int q = 0; q < 4; q++) {
            float2 f0 = __half22float2(a0[q]);
            float2 f1 = __half22float2(a1[q]);
            float2 f2 = __half22float2(a2[q]);
            float2 f3 = __half22float2(a3[q]);
            acc[2 * q]     += w0 * f0.x + w1 * f1.x + w2 * f2.x + w3 * f3.x;
            acc[2 * q + 1] += w0 * f0.y + w1 * f1.y + w2 * f2.y + w3 * f3.y;
        }
    }
    for (; e < end; e++) {
        int s0 = g_esrc[e];
        float w0 = g_dis[s0];
        uint4 v0 = __ldg(&X[(size_t)s0 * 32 + t]);
        const __half2* a0 = (const __half2*)&v0;
#pragma unroll
        for (int q = 0; q < 4; q++) {
            float2 f0 = __half22float2(a0[q]);
            acc[2 * q]     += w0 * f0.x;
            acc[2 * q + 1] += w0 * f0.y;
        }
    }

    float4 b0 = *(const float4*)(b + t * 8);
    float4 b1 = *(const float4*)(b + t * 8 + 4);
    float r[8];
    r[0] = dn * acc[0] + b0.x;  r[1] = dn * acc[1] + b0.y;
    r[2] = dn * acc[2] + b0.z;  r[3] = dn * acc[3] + b0.w;
    r[4] = dn * acc[4] + b1.x;  r[5] = dn * acc[5] + b1.y;
    r[6] = dn * acc[6] + b1.z;  r[7] = dn * acc[7] + b1.w;
#pragma unroll
    for (int q = 0; q < 8; q++)
        r[q] = r[q] > 0.f ? r[q] : expm1f(r[q]);

    if (OUT16) {
        __half2 p0 = __floats2half2_rn(r[0], r[1]);
        __half2 p1 = __floats2half2_rn(r[2], r[3]);
        __half2 p2 = __floats2half2_rn(r[4], r[5]);
        __half2 p3 = __floats2half2_rn(r[6], r[7]);
        uint4 v = make_uint4(*(uint32_t*)&p0, *(uint32_t*)&p1,
                             *(uint32_t*)&p2, *(uint32_t*)&p3);
        *(uint4*)((__half*)outp + (size_t)node * DD + t * 8) = v;
    } else {
        float* O = (float*)outp + (size_t)node * DD + t * 8;
        *(float4*)(O)     = make_float4(r[0], r[1], r[2], r[3]);
        *(float4*)(O + 4) = make_float4(r[4], r[5], r[6], r[7]);
    }
}

// ---------------------------------------------------------------------------
extern "C" void kernel_launch(void* const* d_in, const int* in_sizes, int n_in,
                              void* d_out, int out_size) {
    const float* x   = (const float*)d_in[0];
    const int*   ei  = (const int*)d_in[1];
    const float* W1  = (const float*)d_in[2];
    const float* b1  = (const float*)d_in[3];
    const float* W2  = (const float*)d_in[4];
    const float* b2  = (const float*)d_in[5];
    float*       out = (float*)d_out;

    __half *x16, *xw16, *h16, *w1hi, *w1lo, *w2hi, *w2lo;
    cudaGetSymbolAddress((void**)&x16,  g_x16);
    cudaGetSymbolAddress((void**)&xw16, g_xw16);
    cudaGetSymbolAddress((void**)&h16,  g_h16);
    cudaGetSymbolAddress((void**)&w1hi, g_w1hi);
    cudaGetSymbolAddress((void**)&w1lo, g_w1lo);
    cudaGetSymbolAddress((void**)&w2hi, g_w2hi);
    cudaGetSymbolAddress((void**)&w2lo, g_w2lo);

    const int T = 256;
    int grid_n   = (N_NODES + T - 1) / T;
    int grid_e   = (E_EDGES + T - 1) / T;
    int grid_agg = (N_NODES + 7) / 8;
    int grid_cvt = (N_NODES * DD / 8 + T - 1) / T;
    dim3 gemm_grid(DD / 128, (N_NODES + 127) / 128);

    // Side stream + events: overlap GEMM-path prep + layer-1 GEMM with CSR build.
    cudaStream_t s2;
    cudaStreamCreate(&s2);
    cudaEvent_t evFork, evJoin;
    cudaEventCreateWithFlags(&evFork, cudaEventDisableTiming);
    cudaEventCreateWithFlags(&evJoin, cudaEventDisableTiming);

    cudaEventRecord(evFork, 0);
    cudaStreamWaitEvent(s2, evFork, 0);
    k_cvt_x   <<<grid_cvt, T, 0, s2>>>(x);
    k_wsplit  <<<DD, DD, 0, s2>>>(W1, w1hi, w1lo);
    k_wsplit  <<<DD, DD, 0, s2>>>(W2, w2hi, w2lo);
    k_gemm_mma<<<gemm_grid, T, 0, s2>>>(x16, xw16, w1hi, w1lo, N_NODES);
    cudaEventRecord(evJoin, s2);

    // main stream: edge decode + CSR build + normalization
    k_detect       <<<1, 256>>>(ei);
    k_zero_cnt     <<<grid_n, T>>>();
    k_convert_count<<<grid_e, T>>>(ei);
    k_scan         <<<1, 1024>>>();
    k_fill         <<<grid_e, T>>>();

    // join, then layer 1 aggregation (fp16 out)
    cudaStreamWaitEvent(0, evJoin, 0);
    k_agg<true><<<grid_agg, T>>>(xw16, b1, h16);

    // --- layer 2 ---
    k_gemm_mma<<<gemm_grid, T>>>(h16, xw16, w2hi, w2lo, N_NODES);
    k_agg<false><<<grid_agg, T>>>(xw16, b2, out);

    cudaStreamDestroy(s2);
    cudaEventDestroy(evFork);
    cudaEventDestroy(evJoin);
}

// round 9
// speedup vs baseline: 3.8905x; 1.0872x over previous
#include <cuda_runtime.h>
#include <cuda_fp16.h>
#include <cstdint>
#include <math.h>

// Problem constants (fixed by the reference)
#define N_NODES 100000
#define E_EDGES 3200000
#define DD 256           // feature dim
#define N_SPLIT 50048    // node/row split for layer-boundary pipelining (391*128)

// ---------------- scratch (static device allocations; no cudaMalloc) -------
__device__ int    g_is64;
__device__ int    g_src [E_EDGES];
__device__ int    g_dst [E_EDGES];
__device__ int    g_cnt [N_NODES];
__device__ int    g_off [N_NODES + 1];
__device__ int    g_cur [N_NODES];
__device__ int    g_esrc[E_EDGES];
__device__ float  g_dis [N_NODES];
__device__ __half g_x16 [N_NODES * DD];           // input features, fp16
__device__ __half g_xw16[N_NODES * DD];           // A @ W in fp16 (per layer)
__device__ __half g_h16 [N_NODES * DD];           // layer-1 activations, fp16
__device__ __half g_w1hi[DD * DD], g_w1lo[DD * DD];  // W1^T split [n][k]
__device__ __half g_w2hi[DD * DD], g_w2lo[DD * DD];  // W2^T split [n][k]

// ---------------------------------------------------------------------------
__global__ void k_detect(const int* __restrict__ ei32) {
    __shared__ int nz[256];
    int tid = threadIdx.x;
    int acc = 0;
    for (int i = tid; i < 2048; i += 256)
        acc += (ei32[2 * i + 1] != 0) ? 1 : 0;
    nz[tid] = acc;
    __syncthreads();
    for (int s = 128; s > 0; s >>= 1) {
        if (tid < s) nz[tid] += nz[tid + s];
        __syncthreads();
    }
    if (tid == 0) g_is64 = (nz[0] == 0) ? 1 : 0;
}

__global__ void k_zero_cnt() {
    int i = blockIdx.x * blockDim.x + threadIdx.x;
    if (i < N_NODES) g_cnt[i] = 0;
}

// decode + histogram in one pass
__global__ void k_convert_count(const int* __restrict__ ei32) {
    int e = blockIdx.x * blockDim.x + threadIdx.x;
    if (e >= E_EDGES) return;
    int s, t;
    if (g_is64) {
        s = ei32[2 * e];
        t = ei32[2 * (E_EDGES + e)];
    } else {
        s = ei32[e];
        t = ei32[E_EDGES + e];
    }
    g_src[e] = s;
    g_dst[e] = t;
    atomicAdd(&g_cnt[t], 1);
}

__global__ __launch_bounds__(1024)
void k_scan() {
    __shared__ int sums[1024];
    const int tid = threadIdx.x;
    const int CH  = (N_NODES + 1023) / 1024;
    int beg = tid * CH;
    int end = beg + CH; if (end > N_NODES) end = N_NODES;
    if (beg > N_NODES) beg = N_NODES;

    int s = 0;
    for (int i = beg; i < end; i++) s += g_cnt[i];
    sums[tid] = s;
    __syncthreads();
    for (int off = 1; off < 1024; off <<= 1) {
        int v = (tid >= off) ? sums[tid - off] : 0;
        __syncthreads();
        sums[tid] += v;
        __syncthreads();
    }
    int run = (tid > 0) ? sums[tid - 1] : 0;
    for (int i = beg; i < end; i++) {
        int c = g_cnt[i];
        g_off[i] = run;
        g_cur[i] = run;
        g_dis[i] = rsqrtf((float)(c + 1));
        run += c;
    }
    if (tid == 0) g_off[N_NODES] = sums[1023];
}

__global__ void k_fill() {
    int e = blockIdx.x * blockDim.x + threadIdx.x;
    if (e >= E_EDGES) return;
    int p = atomicAdd(&g_cur[g_dst[e]], 1);
    g_esrc[p] = g_src[e];
}

// ---------------------------------------------------------------------------
// x (fp32) -> fp16 copy; each thread handles 8 elements
__global__ void k_cvt_x(const float* __restrict__ x) {
    int idx = blockIdx.x * blockDim.x + threadIdx.x;
    if (idx >= N_NODES * DD / 8) return;
    float4 a = *(const float4*)(x + idx * 8);
    float4 b = *(const float4*)(x + idx * 8 + 4);
    __half2 p0 = __floats2half2_rn(a.x, a.y);
    __half2 p1 = __floats2half2_rn(a.z, a.w);
    __half2 p2 = __floats2half2_rn(b.x, b.y);
    __half2 p3 = __floats2half2_rn(b.z, b.w);
    uint4 v = make_uint4(*(uint32_t*)&p0, *(uint32_t*)&p1,
                         *(uint32_t*)&p2, *(uint32_t*)&p3);
    *(uint4*)(g_x16 + idx * 8) = v;
}

// W^T split into fp16 hi/lo:  whi[n][k] + wlo[n][k] ~= W[k][n]
__global__ void k_wsplit(const float* __restrict__ W,
                         __half* __restrict__ whi, __half* __restrict__ wlo) {
    int idx = blockIdx.x * blockDim.x + threadIdx.x;
    int n = idx >> 8, k = idx & 255;
    float v = W[k * DD + n];
    __half hi = __float2half_rn(v);
    float lo = v - __half2float(hi);
    whi[n * DD + k] = hi;
    wlo[n * DD + k] = __float2half_rn(lo);
}

// ---------------------------------------------------------------------------
// mma.sync wrapper: m16n8k16 fp16 -> f32
__device__ __forceinline__ void mma_f16(float* c, const uint32_t* a, const uint32_t* b) {
    asm volatile(
        "mma.sync.aligned.m16n8k16.row.col.f32.f16.f16.f32 "
        "{%0,%1,%2,%3}, {%4,%5,%6,%7}, {%8,%9}, {%0,%1,%2,%3};"
        : "+f"(c[0]), "+f"(c[1]), "+f"(c[2]), "+f"(c[3])
        : "r"(a[0]), "r"(a[1]), "r"(a[2]), "r"(a[3]), "r"(b[0]), "r"(b[1]));
}

__device__ __forceinline__ void cp16(uint32_t saddr, const void* g) {
    asm volatile("cp.async.cg.shared.global [%0], [%1], 16;"
                 :: "r"(saddr), "l"(g) : "memory");
}
#define CP_COMMIT() asm volatile("cp.async.commit_group;" ::: "memory")
#define CP_WAIT0()  asm volatile("cp.async.wait_group 0;" ::: "memory")

// fp16 GEMM via mma.sync, cp.async double-buffered.
// C16[rows] = fp16( A16 @ W ), D = A*Whi + A*Wlo (f32 accum).
// CTA tile 128x128, BK=32, 8 warps (4m x 2n), warp tile 32x64.
// smem stride 40 halfs (conflict-free). 2 stages x (A + Bhi + Blo).
#define SA 40
#define STG (128 * SA)               // halfs per array per stage
__global__ __launch_bounds__(256, 2)
void k_gemm_mma(const __half* __restrict__ A, __half* __restrict__ C,
                const __half* __restrict__ Whi, const __half* __restrict__ Wlo,
                int row_base, int M) {
    extern __shared__ __half sm[];   // [2][3][STG]: Af, Bhi, Blo per stage

    const int tid  = threadIdx.x;
    const int wid  = tid >> 5;
    const int lane = tid & 31;
    const int wm   = wid & 3;
    const int wn   = wid >> 2;
    const int row0 = row_base + blockIdx.y * 128;
    const int bn   = blockIdx.x * 128;

    const int lq = lane >> 2;
    const int lr = lane & 3;

    // per-thread staging coords: 512 uint4 per array, 2 per thread (A), 2+2 (B)
    const int sr = tid >> 1;              // 0..127 (paired rows)  -- for A: idx>>2
    (void)sr;

    float acc[2][8][4];
#pragma unroll
    for (int i = 0; i < 2; i++)
#pragma unroll
        for (int j = 0; j < 8; j++)
#pragma unroll
            for (int q = 0; q < 4; q++) acc[i][j][q] = 0.0f;

    uint32_t sbase = (uint32_t)__cvta_generic_to_shared(sm);

    // stage(): issue cp.async for k-block kb into stage p
    auto stage = [&](int p, int kb) {
        uint32_t b0 = sbase + (uint32_t)(p * 3 * STG) * 2u;
#pragma unroll
        for (int it = 0; it < 2; it++) {
            int idx = it * 256 + tid;     // 512 uint4
            int r   = idx >> 2;           // 0..127
            int u   = idx & 3;
            int gr  = row0 + r; if (gr >= M) gr = M - 1;   // clamp (rows unused)
            cp16(b0 + (uint32_t)(r * SA + u * 8) * 2u,
                 A + (size_t)gr * DD + kb + u * 8);
        }
        uint32_t bh = b0 + (uint32_t)STG * 2u;
        uint32_t bl = b0 + (uint32_t)(2 * STG) * 2u;
#pragma unroll
        for (int it = 0; it < 2; it++) {
            int idx = it * 256 + tid;
            int r   = idx >> 2;
            int u   = idx & 3;
            uint32_t o = (uint32_t)(r * SA + u * 8) * 2u;
            cp16(bh + o, Whi + (size_t)(bn + r) * DD + kb + u * 8);
            cp16(bl + o, Wlo + (size_t)(bn + r) * DD + kb + u * 8);
        }
        CP_COMMIT();
    };

    stage(0, 0);

    const int NK = DD / 32;              // 8 k-blocks
    for (int i = 0; i < NK; i++) {
        CP_WAIT0();
        __syncthreads();                 // stage(i) visible; all warps past compute(i-1)
        if (i + 1 < NK) stage((i + 1) & 1, (i + 1) * 32);

        const __half* Af  = sm + (i & 1) * 3 * STG;
        const __half* Bhi = Af + STG;
        const __half* Blo = Af + 2 * STG;

#pragma unroll
        for (int ks = 0; ks < 2; ks++) {
            const int k0 = ks * 16;
            uint32_t fbh[8][2], fbl[8][2];
#pragma unroll
            for (int j = 0; j < 8; j++) {
                int n0 = wn * 64 + j * 8;
                int o0 = (n0 + lq) * SA + k0 + lr * 2;
                fbh[j][0] = *(const uint32_t*)(Bhi + o0);
                fbh[j][1] = *(const uint32_t*)(Bhi + o0 + 8);
                fbl[j][0] = *(const uint32_t*)(Blo + o0);
                fbl[j][1] = *(const uint32_t*)(Blo + o0 + 8);
            }
#pragma unroll
            for (int ii = 0; ii < 2; ii++) {
                int m0 = wm * 32 + ii * 16;
                int oa = (m0 + lq) * SA + k0 + lr * 2;
                uint32_t fa[4];
                fa[0] = *(const uint32_t*)(Af + oa);
                fa[1] = *(const uint32_t*)(Af + oa + 8 * SA);
                fa[2] = *(const uint32_t*)(Af + oa + 8);
                fa[3] = *(const uint32_t*)(Af + oa + 8 * SA + 8);
#pragma unroll
                for (int j = 0; j < 8; j++) {
                    mma_f16(acc[ii][j], fa, fbh[j]);
                    mma_f16(acc[ii][j], fa, fbl[j]);
                }
            }
        }
    }

    // ---- epilogue: store fp16 (un-scaled; dis applied in aggregation) ----
#pragma unroll
    for (int i = 0; i < 2; i++) {
        int r_lo = row0 + wm * 32 + i * 16 + lq;
        int r_hi = r_lo + 8;
#pragma unroll
        for (int j = 0; j < 8; j++) {
            int col = bn + wn * 64 + j * 8 + lr * 2;
            if (r_lo < M) {
                __half2 p = __floats2half2_rn(acc[i][j][0], acc[i][j][1]);
                *(uint32_t*)(C + (size_t)r_lo * DD + col) = *(uint32_t*)&p;
            }
            if (r_hi < M) {
                __half2 p = __floats2half2_rn(acc[i][j][2], acc[i][j][3]);
                *(uint32_t*)(C + (size_t)r_hi * DD + col) = *(uint32_t*)&p;
            }
        }
    }
}
#define GEMM_SMEM (2 * 3 * STG * 2)   // bytes = 61440

// ---------------------------------------------------------------------------
// Fused aggregate + norm + bias + ELU from fp16 features.
// 8 nodes per 256-thread block, 32 threads/node, one uint4 (8 halfs) per thread.
template <bool OUT16>
__global__ __launch_bounds__(256)
void k_agg(const __half* __restrict__ xw16, const float* __restrict__ b,
           void* __restrict__ outp, int node_base, int node_cnt) {
    int node = node_base + blockIdx.x * 8 + (threadIdx.x >> 5);
    if (node >= node_base + node_cnt) return;
    int t = threadIdx.x & 31;

    const uint4* X = (const uint4*)xw16;

    float dn = g_dis[node];
    float acc[8];
    {
        uint4 v = __ldg(&X[(size_t)node * 32 + t]);
        const __half2* h2 = (const __half2*)&v;
#pragma unroll
        for (int q = 0; q < 4; q++) {
            float2 f = __half22float2(h2[q]);
            acc[2 * q]     = dn * f.x;
            acc[2 * q + 1] = dn * f.y;
        }
    }

    int beg = g_off[node];
    int end = g_off[node + 1];

    int e = beg;
    for (; e + 8 <= end; e += 8) {
        int s[8];
#pragma unroll
        for (int q = 0; q < 8; q++) s[q] = g_esrc[e + q];
        float w[8];
#pragma unroll
        for (int q = 0; q < 8; q++) w[q] = g_dis[s[q]];
        uint4 v[8];
#pragma unroll
        for (int q = 0; q < 8; q++) v[q] = __ldg(&X[(size_t)s[q] * 32 + t]);
#pragma unroll
        for (int q = 0; q < 8; q++) {
            const __half2* a = (const __half2*)&v[q];
#pragma unroll
            for (int p = 0; p < 4; p++) {
                float2 f = __half22float2(a[p]);
                acc[2 * p]     += w[q] * f.x;
                acc[2 * p + 1] += w[q] * f.y;
            }
        }
    }
    for (; e < end; e++) {
        int s0 = g_esrc[e];
        float w0 = g_dis[s0];
        uint4 v0 = __ldg(&X[(size_t)s0 * 32 + t]);
        const __half2* a0 = (const __half2*)&v0;
#pragma unroll
        for (int q = 0; q < 4; q++) {
            float2 f0 = __half22float2(a0[q]);
            acc[2 * q]     += w0 * f0.x;
            acc[2 * q + 1] += w0 * f0.y;
        }
    }

    float4 b0 = *(const float4*)(b + t * 8);
    float4 b1 = *(const float4*)(b + t * 8 + 4);
    float r[8];
    r[0] = dn * acc[0] + b0.x;  r[1] = dn * acc[1] + b0.y;
    r[2] = dn * acc[2] + b0.z;  r[3] = dn * acc[3] + b0.w;
    r[4] = dn * acc[4] + b1.x;  r[5] = dn * acc[5] + b1.y;
    r[6] = dn * acc[6] + b1.z;  r[7] = dn * acc[7] + b1.w;
#pragma unroll
    for (int q = 0; q < 8; q++)
        r[q] = r[q] > 0.f ? r[q] : expm1f(r[q]);

    if (OUT16) {
        __half2 p0 = __floats2half2_rn(r[0], r[1]);
        __half2 p1 = __floats2half2_rn(r[2], r[3]);
        __half2 p2 = __floats2half2_rn(r[4], r[5]);
        __half2 p3 = __floats2half2_rn(r[6], r[7]);
        uint4 v = make_uint4(*(uint32_t*)&p0, *(uint32_t*)&p1,
                             *(uint32_t*)&p2, *(uint32_t*)&p3);
        *(uint4*)((__half*)outp + (size_t)node * DD + t * 8) = v;
    } else {
        float* O = (float*)outp + (size_t)node * DD + t * 8;
        *(float4*)(O)     = make_float4(r[0], r[1], r[2], r[3]);
        *(float4*)(O + 4) = make_float4(r[4], r[5], r[6], r[7]);
    }
}

// ---------------------------------------------------------------------------
extern "C" void kernel_launch(void* const* d_in, const int* in_sizes, int n_in,
                              void* d_out, int out_size) {
    const float* x   = (const float*)d_in[0];
    const int*   ei  = (const int*)d_in[1];
    const float* W1  = (const float*)d_in[2];
    const float* b1  = (const float*)d_in[3];
    const float* W2  = (const float*)d_in[4];
    const float* b2  = (const float*)d_in[5];
    float*       out = (float*)d_out;

    __half *x16, *xw16, *h16, *w1hi, *w1lo, *w2hi, *w2lo;
    cudaGetSymbolAddress((void**)&x16,  g_x16);
    cudaGetSymbolAddress((void**)&xw16, g_xw16);
    cudaGetSymbolAddress((void**)&h16,  g_h16);
    cudaGetSymbolAddress((void**)&w1hi, g_w1hi);
    cudaGetSymbolAddress((void**)&w1lo, g_w1lo);
    cudaGetSymbolAddress((void**)&w2hi, g_w2hi);
    cudaGetSymbolAddress((void**)&w2lo, g_w2lo);

    cudaFuncSetAttribute(k_gemm_mma,
                         cudaFuncAttributeMaxDynamicSharedMemorySize, GEMM_SMEM);

    const int T = 256;
    int grid_n   = (N_NODES + T - 1) / T;
    int grid_e   = (E_EDGES + T - 1) / T;
    int grid_cvt = (N_NODES * DD / 8 + T - 1) / T;

    const int N2 = N_NODES - N_SPLIT;
    dim3 gemm_all (DD / 128, (N_NODES + 127) / 128);
    dim3 gemm_half(DD / 128, N_SPLIT / 128);
    dim3 gemm_rem (DD / 128, (N2 + 127) / 128);
    int agg_all  = (N_NODES + 7) / 8;
    int agg_half = (N_SPLIT + 7) / 8;
    int agg_rem  = (N2 + 7) / 8;

    cudaStream_t s2;
    cudaStreamCreate(&s2);
    cudaEvent_t evFork, evW, evJoin, evA1a, evG2a;
    cudaEventCreateWithFlags(&evFork, cudaEventDisableTiming);
    cudaEventCreateWithFlags(&evW,    cudaEventDisableTiming);
    cudaEventCreateWithFlags(&evJoin, cudaEventDisableTiming);
    cudaEventCreateWithFlags(&evA1a,  cudaEventDisableTiming);
    cudaEventCreateWithFlags(&evG2a,  cudaEventDisableTiming);

    // fork side stream
    cudaEventRecord(evFork, 0);
    cudaStreamWaitEvent(s2, evFork, 0);

    // main: weight splits first (cheap, feed GEMM-1), then CSR build
    k_wsplit<<<DD, DD>>>(W1, w1hi, w1lo);
    k_wsplit<<<DD, DD>>>(W2, w2hi, w2lo);
    cudaEventRecord(evW, 0);

    // s2: x conversion, then layer-1 GEMM (waits on weights only)
    k_cvt_x<<<grid_cvt, T, 0, s2>>>(x);
    cudaStreamWaitEvent(s2, evW, 0);
    k_gemm_mma<<<gemm_all, T, GEMM_SMEM, s2>>>(x16, xw16, w1hi, w1lo, 0, N_NODES);
    cudaEventRecord(evJoin, s2);

    // main: edge decode + CSR build + normalization (overlaps with s2)
    k_detect       <<<1, 256>>>(ei);
    k_zero_cnt     <<<grid_n, T>>>();
    k_convert_count<<<grid_e, T>>>(ei);
    k_scan         <<<1, 1024>>>();
    k_fill         <<<grid_e, T>>>();

    // join; layer-1 aggregation split into halves for layer-boundary overlap
    cudaStreamWaitEvent(0, evJoin, 0);
    k_agg<true><<<agg_half, T>>>(xw16, b1, h16, 0, N_SPLIT);
    cudaEventRecord(evA1a, 0);
    k_agg<true><<<agg_rem, T>>>(xw16, b1, h16, N_SPLIT, N2);

    // s2: GEMM-2 on first half rows while main finishes agg-1 second half
    cudaStreamWaitEvent(s2, evA1a, 0);
    k_gemm_mma<<<gemm_half, T, GEMM_SMEM, s2>>>(h16, xw16, w2hi, w2lo, 0, N_NODES);
    cudaEventRecord(evG2a, s2);

    // main: GEMM-2 on remaining rows, then full layer-2 aggregation
    k_gemm_mma<<<gemm_rem, T, GEMM_SMEM>>>(h16, xw16, w2hi, w2lo, N_SPLIT, N_NODES);
    cudaStreamWaitEvent(0, evG2a, 0);
    k_agg<false><<<agg_all, T>>>(xw16, b2, out, 0, N_NODES);

    cudaStreamDestroy(s2);
    cudaEventDestroy(evFork);
    cudaEventDestroy(evW);
    cudaEventDestroy(evJoin);
    cudaEventDestroy(evA1a);
    cudaEventDestroy(evG2a);
}

// round 10
// speedup vs baseline: 4.3264x; 1.1120x over previous
#include <cuda_runtime.h>
#include <cuda_fp16.h>
#include <cstdint>
#include <math.h>

// Problem constants (fixed by the reference)
#define N_NODES 100000
#define E_EDGES 3200000
#define DD 256           // feature dim
#define N_SPLIT 50048    // node/row split for layer-boundary pipelining (391*128)

// ---------------- scratch (static device allocations; no cudaMalloc) -------
__device__ int    g_is64;
__device__ int    g_src [E_EDGES];
__device__ int    g_dst [E_EDGES];
__device__ int    g_cnt [N_NODES];
__device__ int    g_off [N_NODES + 1];
__device__ int    g_cur [N_NODES];
__device__ int    g_esrc[E_EDGES];
__device__ float  g_dis [N_NODES];
__device__ __half g_x16 [N_NODES * DD];           // input features, fp16
__device__ __half g_xw16[N_NODES * DD];           // A @ W in fp16 (per layer)
__device__ __half g_h16 [N_NODES * DD];           // layer-1 activations, fp16
__device__ __half g_w1t [DD * DD];                // W1^T fp16 [n][k]
__device__ __half g_w2t [DD * DD];                // W2^T fp16 [n][k]

// ---------------------------------------------------------------------------
__global__ void k_detect(const int* __restrict__ ei32) {
    __shared__ int nz[256];
    int tid = threadIdx.x;
    int acc = 0;
    for (int i = tid; i < 2048; i += 256)
        acc += (ei32[2 * i + 1] != 0) ? 1 : 0;
    nz[tid] = acc;
    __syncthreads();
    for (int s = 128; s > 0; s >>= 1) {
        if (tid < s) nz[tid] += nz[tid + s];
        __syncthreads();
    }
    if (tid == 0) g_is64 = (nz[0] == 0) ? 1 : 0;
}

__global__ void k_zero_cnt() {
    int i = blockIdx.x * blockDim.x + threadIdx.x;
    if (i < N_NODES) g_cnt[i] = 0;
}

// decode + histogram in one pass
__global__ void k_convert_count(const int* __restrict__ ei32) {
    int e = blockIdx.x * blockDim.x + threadIdx.x;
    if (e >= E_EDGES) return;
    int s, t;
    if (g_is64) {
        s = ei32[2 * e];
        t = ei32[2 * (E_EDGES + e)];
    } else {
        s = ei32[e];
        t = ei32[E_EDGES + e];
    }
    g_src[e] = s;
    g_dst[e] = t;
    atomicAdd(&g_cnt[t], 1);
}

__global__ __launch_bounds__(1024)
void k_scan() {
    __shared__ int sums[1024];
    const int tid = threadIdx.x;
    const int CH  = (N_NODES + 1023) / 1024;
    int beg = tid * CH;
    int end = beg + CH; if (end > N_NODES) end = N_NODES;
    if (beg > N_NODES) beg = N_NODES;

    int s = 0;
    for (int i = beg; i < end; i++) s += g_cnt[i];
    sums[tid] = s;
    __syncthreads();
    for (int off = 1; off < 1024; off <<= 1) {
        int v = (tid >= off) ? sums[tid - off] : 0;
        __syncthreads();
        sums[tid] += v;
        __syncthreads();
    }
    int run = (tid > 0) ? sums[tid - 1] : 0;
    for (int i = beg; i < end; i++) {
        int c = g_cnt[i];
        g_off[i] = run;
        g_cur[i] = run;
        g_dis[i] = rsqrtf((float)(c + 1));
        run += c;
    }
    if (tid == 0) g_off[N_NODES] = sums[1023];
}

__global__ void k_fill() {
    int e = blockIdx.x * blockDim.x + threadIdx.x;
    if (e >= E_EDGES) return;
    int p = atomicAdd(&g_cur[g_dst[e]], 1);
    g_esrc[p] = g_src[e];
}

// ---------------------------------------------------------------------------
// x (fp32) -> fp16 copy; each thread handles 8 elements
__global__ void k_cvt_x(const float* __restrict__ x) {
    int idx = blockIdx.x * blockDim.x + threadIdx.x;
    if (idx >= N_NODES * DD / 8) return;
    float4 a = *(const float4*)(x + idx * 8);
    float4 b = *(const float4*)(x + idx * 8 + 4);
    __half2 p0 = __floats2half2_rn(a.x, a.y);
    __half2 p1 = __floats2half2_rn(a.z, a.w);
    __half2 p2 = __floats2half2_rn(b.x, b.y);
    __half2 p3 = __floats2half2_rn(b.z, b.w);
    uint4 v = make_uint4(*(uint32_t*)&p0, *(uint32_t*)&p1,
                         *(uint32_t*)&p2, *(uint32_t*)&p3);
    *(uint4*)(g_x16 + idx * 8) = v;
}

// W^T -> fp16:  wt[n][k] = fp16(W[k][n])
__global__ void k_wcvt(const float* __restrict__ W, __half* __restrict__ wt) {
    int idx = blockIdx.x * blockDim.x + threadIdx.x;
    int n = idx >> 8, k = idx & 255;
    wt[n * DD + k] = __float2half_rn(W[k * DD + n]);
}

// ---------------------------------------------------------------------------
// mma.sync wrapper: m16n8k16 fp16 -> f32
__device__ __forceinline__ void mma_f16(float* c, const uint32_t* a, const uint32_t* b) {
    asm volatile(
        "mma.sync.aligned.m16n8k16.row.col.f32.f16.f16.f32 "
        "{%0,%1,%2,%3}, {%4,%5,%6,%7}, {%8,%9}, {%0,%1,%2,%3};"
        : "+f"(c[0]), "+f"(c[1]), "+f"(c[2]), "+f"(c[3])
        : "r"(a[0]), "r"(a[1]), "r"(a[2]), "r"(a[3]), "r"(b[0]), "r"(b[1]));
}

__device__ __forceinline__ void ldsm4(uint32_t* r, uint32_t saddr) {
    asm volatile("ldmatrix.sync.aligned.m8n8.x4.shared.b16 {%0,%1,%2,%3}, [%4];"
                 : "=r"(r[0]), "=r"(r[1]), "=r"(r[2]), "=r"(r[3]) : "r"(saddr));
}

__device__ __forceinline__ void cp16(uint32_t saddr, const void* g) {
    asm volatile("cp.async.cg.shared.global [%0], [%1], 16;"
                 :: "r"(saddr), "l"(g) : "memory");
}
#define CP_COMMIT() asm volatile("cp.async.commit_group;" ::: "memory")
#define CP_WAIT0()  asm volatile("cp.async.wait_group 0;" ::: "memory")

// fp16 GEMM via mma.sync + ldmatrix, cp.async double-buffered, single term.
// C16[rows] = fp16( A16 @ W16 ).  CTA tile 128x128, BK=32, 8 warps (4m x 2n),
// warp tile 32x64. smem stride 40 halfs (conflict-free for LDS and LDSM).
#define SA 40
#define STG (128 * SA)               // halfs per array per stage
__global__ __launch_bounds__(256, 2)
void k_gemm_mma(const __half* __restrict__ A, __half* __restrict__ C,
                const __half* __restrict__ Wt, int row_base, int M) {
    extern __shared__ __half sm[];   // [2][2][STG]: Af, Bf per stage

    const int tid  = threadIdx.x;
    const int wid  = tid >> 5;
    const int lane = tid & 31;
    const int wm   = wid & 3;
    const int wn   = wid >> 2;
    const int row0 = row_base + blockIdx.y * 128;
    const int bn   = blockIdx.x * 128;

    float acc[2][8][4];
#pragma unroll
    for (int i = 0; i < 2; i++)
#pragma unroll
        for (int j = 0; j < 8; j++)
#pragma unroll
            for (int q = 0; q < 4; q++) acc[i][j][q] = 0.0f;

    uint32_t sbase = (uint32_t)__cvta_generic_to_shared(sm);

    // ldmatrix per-lane address components (in halfs, converted to bytes below)
    const int a_r = lane & 15;             // row within 16-row A frag group
    const int a_k = (lane >> 4) << 3;      // 0 or 8
    const int b_r = ((lane >> 4) << 3) + (lane & 7);  // n-row within pair group
    const int b_k = ((lane >> 3) & 1) << 3;           // 0 or 8

    auto stage = [&](int p, int kb) {
        uint32_t bA = sbase + (uint32_t)(p * 2 * STG) * 2u;
        uint32_t bB = bA + (uint32_t)STG * 2u;
#pragma unroll
        for (int it = 0; it < 2; it++) {
            int idx = it * 256 + tid;     // 512 uint4
            int r   = idx >> 2;           // 0..127
            int u   = idx & 3;
            int gr  = row0 + r; if (gr >= M) gr = M - 1;   // clamp (rows unused)
            cp16(bA + (uint32_t)(r * SA + u * 8) * 2u,
                 A + (size_t)gr * DD + kb + u * 8);
            cp16(bB + (uint32_t)(r * SA + u * 8) * 2u,
                 Wt + (size_t)(bn + r) * DD + kb + u * 8);
        }
        CP_COMMIT();
    };

    stage(0, 0);

    const int NK = DD / 32;              // 8 k-blocks
    for (int i = 0; i < NK; i++) {
        CP_WAIT0();
        __syncthreads();
        if (i + 1 < NK) stage((i + 1) & 1, (i + 1) * 32);

        uint32_t sAf = sbase + (uint32_t)((i & 1) * 2 * STG) * 2u;
        uint32_t sBf = sAf + (uint32_t)STG * 2u;

#pragma unroll
        for (int ks = 0; ks < 2; ks++) {
            const int k0 = ks * 16;
            // B fragments: 4 ldmatrix.x4 -> 8 n-tiles x 2 k-frags
            uint32_t fb[8][2];
#pragma unroll
            for (int jp = 0; jp < 4; jp++) {
                int nj = wn * 64 + jp * 16;
                uint32_t addr = sBf + (uint32_t)((nj + b_r) * SA + k0 + b_k) * 2u;
                uint32_t r4[4];
                ldsm4(r4, addr);
                fb[jp * 2][0]     = r4[0];
                fb[jp * 2][1]     = r4[1];
                fb[jp * 2 + 1][0] = r4[2];
                fb[jp * 2 + 1][1] = r4[3];
            }
#pragma unroll
            for (int ii = 0; ii < 2; ii++) {
                int m0 = wm * 32 + ii * 16;
                uint32_t addr = sAf + (uint32_t)((m0 + a_r) * SA + k0 + a_k) * 2u;
                uint32_t fa[4];
                ldsm4(fa, addr);
#pragma unroll
                for (int j = 0; j < 8; j++)
                    mma_f16(acc[ii][j], fa, fb[j]);
            }
        }
    }

    // ---- epilogue: store fp16 (un-scaled; dis applied in aggregation) ----
    const int lq = lane >> 2;
    const int lr = lane & 3;
#pragma unroll
    for (int i = 0; i < 2; i++) {
        int r_lo = row0 + wm * 32 + i * 16 + lq;
        int r_hi = r_lo + 8;
#pragma unroll
        for (int j = 0; j < 8; j++) {
            int col = bn + wn * 64 + j * 8 + lr * 2;
            if (r_lo < M) {
                __half2 p = __floats2half2_rn(acc[i][j][0], acc[i][j][1]);
                *(uint32_t*)(C + (size_t)r_lo * DD + col) = *(uint32_t*)&p;
            }
            if (r_hi < M) {
                __half2 p = __floats2half2_rn(acc[i][j][2], acc[i][j][3]);
                *(uint32_t*)(C + (size_t)r_hi * DD + col) = *(uint32_t*)&p;
            }
        }
    }
}
#define GEMM_SMEM (2 * 2 * STG * 2)   // bytes = 40960

// ---------------------------------------------------------------------------
// Fused aggregate + norm + bias + ELU from fp16 features.
// 8 nodes per 256-thread block, 32 threads/node, one uint4 (8 halfs) per thread.
template <bool OUT16>
__global__ __launch_bounds__(256)
void k_agg(const __half* __restrict__ xw16, const float* __restrict__ b,
           void* __restrict__ outp, int node_base, int node_cnt) {
    int node = node_base + blockIdx.x * 8 + (threadIdx.x >> 5);
    if (node >= node_base + node_cnt) return;
    int t = threadIdx.x & 31;

    const uint4* X = (const uint4*)xw16;

    float dn = g_dis[node];
    float acc[8];
    {
        uint4 v = __ldg(&X[(size_t)node * 32 + t]);
        const __half2* h2 = (const __half2*)&v;
#pragma unroll
        for (int q = 0; q < 4; q++) {
            float2 f = __half22float2(h2[q]);
            acc[2 * q]     = dn * f.x;
            acc[2 * q + 1] = dn * f.y;
        }
    }

    int beg = g_off[node];
    int end = g_off[node + 1];

    int e = beg;
    for (; e + 8 <= end; e += 8) {
        int s[8];
#pragma unroll
        for (int q = 0; q < 8; q++) s[q] = g_esrc[e + q];
        float w[8];
#pragma unroll
        for (int q = 0; q < 8; q++) w[q] = g_dis[s[q]];
        uint4 v[8];
#pragma unroll
        for (int q = 0; q < 8; q++) v[q] = __ldg(&X[(size_t)s[q] * 32 + t]);
#pragma unroll
        for (int q = 0; q < 8; q++) {
            const __half2* a = (const __half2*)&v[q];
#pragma unroll
            for (int p = 0; p < 4; p++) {
                float2 f = __half22float2(a[p]);
                acc[2 * p]     += w[q] * f.x;
                acc[2 * p + 1] += w[q] * f.y;
            }
        }
    }
    for (; e < end; e++) {
        int s0 = g_esrc[e];
        float w0 = g_dis[s0];
        uint4 v0 = __ldg(&X[(size_t)s0 * 32 + t]);
        const __half2* a0 = (const __half2*)&v0;
#pragma unroll
        for (int q = 0; q < 4; q++) {
            float2 f0 = __half22float2(a0[q]);
            acc[2 * q]     += w0 * f0.x;
            acc[2 * q + 1] += w0 * f0.y;
        }
    }

    float4 b0 = *(const float4*)(b + t * 8);
    float4 b1 = *(const float4*)(b + t * 8 + 4);
    float r[8];
    r[0] = dn * acc[0] + b0.x;  r[1] = dn * acc[1] + b0.y;
    r[2] = dn * acc[2] + b0.z;  r[3] = dn * acc[3] + b0.w;
    r[4] = dn * acc[4] + b1.x;  r[5] = dn * acc[5] + b1.y;
    r[6] = dn * acc[6] + b1.z;  r[7] = dn * acc[7] + b1.w;
#pragma unroll
    for (int q = 0; q < 8; q++)
        r[q] = r[q] > 0.f ? r[q] : expm1f(r[q]);

    if (OUT16) {
        __half2 p0 = __floats2half2_rn(r[0], r[1]);
        __half2 p1 = __floats2half2_rn(r[2], r[3]);
        __half2 p2 = __floats2half2_rn(r[4], r[5]);
        __half2 p3 = __floats2half2_rn(r[6], r[7]);
        uint4 v = make_uint4(*(uint32_t*)&p0, *(uint32_t*)&p1,
                             *(uint32_t*)&p2, *(uint32_t*)&p3);
        *(uint4*)((__half*)outp + (size_t)node * DD + t * 8) = v;
    } else {
        float* O = (float*)outp + (size_t)node * DD + t * 8;
        *(float4*)(O)     = make_float4(r[0], r[1], r[2], r[3]);
        *(float4*)(O + 4) = make_float4(r[4], r[5], r[6], r[7]);
    }
}

// ---------------------------------------------------------------------------
extern "C" void kernel_launch(void* const* d_in, const int* in_sizes, int n_in,
                              void* d_out, int out_size) {
    const float* x   = (const float*)d_in[0];
    const int*   ei  = (const int*)d_in[1];
    const float* W1  = (const float*)d_in[2];
    const float* b1  = (const float*)d_in[3];
    const float* W2  = (const float*)d_in[4];
    const float* b2  = (const float*)d_in[5];
    float*       out = (float*)d_out;

    __half *x16, *xw16, *h16, *w1t, *w2t;
    cudaGetSymbolAddress((void**)&x16,  g_x16);
    cudaGetSymbolAddress((void**)&xw16, g_xw16);
    cudaGetSymbolAddress((void**)&h16,  g_h16);
    cudaGetSymbolAddress((void**)&w1t,  g_w1t);
    cudaGetSymbolAddress((void**)&w2t,  g_w2t);

    cudaFuncSetAttribute(k_gemm_mma,
                         cudaFuncAttributeMaxDynamicSharedMemorySize, GEMM_SMEM);

    const int T = 256;
    int grid_n   = (N_NODES + T - 1) / T;
    int grid_e   = (E_EDGES + T - 1) / T;
    int grid_cvt = (N_NODES * DD / 8 + T - 1) / T;

    const int N2 = N_NODES - N_SPLIT;
    dim3 gemm_all (DD / 128, (N_NODES + 127) / 128);
    dim3 gemm_half(DD / 128, N_SPLIT / 128);
    dim3 gemm_rem (DD / 128, (N2 + 127) / 128);
    int agg_all  = (N_NODES + 7) / 8;
    int agg_half = (N_SPLIT + 7) / 8;
    int agg_rem  = (N2 + 7) / 8;

    cudaStream_t s2;
    cudaStreamCreate(&s2);
    cudaEvent_t evFork, evW, evJoin, evA1a, evG2a;
    cudaEventCreateWithFlags(&evFork, cudaEventDisableTiming);
    cudaEventCreateWithFlags(&evW,    cudaEventDisableTiming);
    cudaEventCreateWithFlags(&evJoin, cudaEventDisableTiming);
    cudaEventCreateWithFlags(&evA1a,  cudaEventDisableTiming);
    cudaEventCreateWithFlags(&evG2a,  cudaEventDisableTiming);

    // fork side stream
    cudaEventRecord(evFork, 0);
    cudaStreamWaitEvent(s2, evFork, 0);

    // main: weight conversions first (cheap, feed GEMMs), then CSR build
    k_wcvt<<<DD, DD>>>(W1, w1t);
    k_wcvt<<<DD, DD>>>(W2, w2t);
    cudaEventRecord(evW, 0);

    // s2: x conversion, then layer-1 GEMM (waits on weights only)
    k_cvt_x<<<grid_cvt, T, 0, s2>>>(x);
    cudaStreamWaitEvent(s2, evW, 0);
    k_gemm_mma<<<gemm_all, T, GEMM_SMEM, s2>>>(x16, xw16, w1t, 0, N_NODES);
    cudaEventRecord(evJoin, s2);

    // main: edge decode + CSR build + normalization (overlaps with s2)
    k_detect       <<<1, 256>>>(ei);
    k_zero_cnt     <<<grid_n, T>>>();
    k_convert_count<<<grid_e, T>>>(ei);
    k_scan         <<<1, 1024>>>();
    k_fill         <<<grid_e, T>>>();

    // join; layer-1 aggregation split into halves for layer-boundary overlap
    cudaStreamWaitEvent(0, evJoin, 0);
    k_agg<true><<<agg_half, T>>>(xw16, b1, h16, 0, N_SPLIT);
    cudaEventRecord(evA1a, 0);
    k_agg<true><<<agg_rem, T>>>(xw16, b1, h16, N_SPLIT, N2);

    // s2: GEMM-2 on first half rows while main finishes agg-1 second half
    cudaStreamWaitEvent(s2, evA1a, 0);
    k_gemm_mma<<<gemm_half, T, GEMM_SMEM, s2>>>(h16, xw16, w2t, 0, N_NODES);
    cudaEventRecord(evG2a, s2);

    // main: GEMM-2 on remaining rows, then full layer-2 aggregation
    k_gemm_mma<<<gemm_rem, T, GEMM_SMEM>>>(h16, xw16, w2t, N_SPLIT, N_NODES);
    cudaStreamWaitEvent(0, evG2a, 0);
    k_agg<false><<<agg_all, T>>>(xw16, b2, out, 0, N_NODES);

    cudaStreamDestroy(s2);
    cudaEventDestroy(evFork);
    cudaEventDestroy(evW);
    cudaEventDestroy(evJoin);
    cudaEventDestroy(evA1a);
    cudaEventDestroy(evG2a);
}